// round 3
// baseline (speedup 1.0000x reference)
#include <cuda_runtime.h>
#include <math.h>

#define TT    64     // t-rows per block tile
#define CT    128    // channels per block tile
#define HALO  56     // max conv radius
#define ROWS  (TT + 2*HALO)   // 176
#define NTHREADS 256
#define RCHUNK 8     // outputs per thread per chunk

// ---------------- compile-time Gaussian bank ----------------
__host__ __device__ constexpr double cexp_(double x) {
    // exp(x) for x in [-10, 0]: range-reduce by 256, Taylor, square 8x
    double y = x / 256.0;
    double s = 1.0, term = 1.0;
    for (int n = 1; n <= 24; ++n) { term = term * y / (double)n; s += term; }
    for (int i = 0; i < 8; ++i) s = s * s;
    return s;
}

struct BankT { float w[5][113]; };

__host__ __device__ constexpr BankT make_bank() {
    BankT b{};
    double sig[5] = {2.5, 4.0, 6.0, 9.0, 14.0};
    for (int k = 0; k < 5; ++k) {
        double s = sig[k];
        int r = (int)(4.0 * s);          // 10,16,24,36,56
        double sum = 0.0;
        for (int d = -r; d <= r; ++d) sum += cexp_(-0.5 * ((double)d / s) * ((double)d / s));
        for (int d = -r; d <= r; ++d)
            b.w[k][56 + d] = (float)(cexp_(-0.5 * ((double)d / s) * ((double)d / s)) / sum);
    }
    return b;
}

// ---------------- kernel ----------------
__global__ void __launch_bounds__(NTHREADS, 2)
agt_kernel(const float* __restrict__ x, const float* __restrict__ W1,
           const float* __restrict__ b1, const float* __restrict__ W2,
           const float* __restrict__ b2, float* __restrict__ out,
           int B, int T, int C)
{
    constexpr BankT BANK = make_bank();
    constexpr int RAD[5] = {10, 16, 24, 36, 56};

    extern __shared__ float sm[];
    float* S  = sm;                // ROWS * CT tile
    float* ws = sm + ROWS * CT;    // 293 weights

    const int tx  = threadIdx.x;           // channel within tile
    const int ty  = threadIdx.y;           // t-half within tile
    const int tid = ty * CT + tx;
    const int c0  = blockIdx.x * CT;
    const int t0  = blockIdx.y * TT;
    const int bb  = blockIdx.z;

    // --- stage weights into smem: [W1(96) | b1(32) | W2(160) | b2(5)] ---
    for (int i = tid; i < 293; i += NTHREADS) {
        float v;
        if      (i <  96) v = W1[i];
        else if (i < 128) v = b1[i - 96];
        else if (i < 288) v = W2[i - 128];
        else              v = b2[i - 288];
        ws[i] = v;
    }

    // --- stage x tile (zero padded outside [0,T) for the conv) ---
    const float* xb = x + ((size_t)bb * T) * C + c0;
    for (int idx = tid; idx < ROWS * CT; idx += NTHREADS) {
        int r  = idx >> 7;         // / CT
        int cc = idx & (CT - 1);
        int g  = t0 - HALO + r;
        float v = 0.0f;
        if (g >= 0 && g < T) v = xb[(size_t)g * C + cc];
        S[idx] = v;
    }
    __syncthreads();

    #pragma unroll 1
    for (int chunk = 0; chunk < TT / (2 * RCHUNK); ++chunk) {
        const int lb = ty * (TT / 2) + chunk * RCHUNK;  // local first output row
        const int tb = t0 + lb;                         // global first output row

        // ---------- 5-sigma conv (streaming, immediate-coefficient FFMA) ----------
        float Y[RCHUNK][5];
        #pragma unroll
        for (int i = 0; i < RCHUNK; ++i)
            #pragma unroll
            for (int k = 0; k < 5; ++k) Y[i][k] = 0.0f;

        #pragma unroll
        for (int jj = 0; jj < RCHUNK + 2 * HALO; ++jj) {   // 120 input rows
            float v = S[(lb + jj) * CT + tx];
            #pragma unroll
            for (int i = 0; i < RCHUNK; ++i) {
                const int d = jj - HALO - i;
                #pragma unroll
                for (int k = 0; k < 5; ++k) {
                    if (d >= -RAD[k] && d <= RAD[k])
                        Y[i][k] += v * BANK.w[k][56 + d];
                }
            }
        }

        // ---------- mean / var over 16-window, reflect padding ----------
        float m[RCHUNK], va[RCHUNK], xv[RCHUNK];
        {
            float s = 0.0f, s2 = 0.0f;
            #pragma unroll
            for (int u = -7; u <= 8; ++u) {
                int g = tb + u;
                g = (g < 0)  ? -g            : g;
                g = (g >= T) ? (2 * T - 2 - g) : g;
                float w = S[(g - t0 + HALO) * CT + tx];
                s += w; s2 += w * w;
            }
            #pragma unroll
            for (int i = 0; i < RCHUNK; ++i) {
                if (i > 0) {
                    int ga = tb + i + 8;  ga = (ga >= T) ? (2 * T - 2 - ga) : ga;
                    int gr = tb + i - 8;  gr = (gr < 0)  ? -gr              : gr;
                    float wa = S[(ga - t0 + HALO) * CT + tx];
                    float wr = S[(gr - t0 + HALO) * CT + tx];
                    s  += wa - wr;
                    s2 += wa * wa - wr * wr;
                }
                float mm = s  * (1.0f / 16.0f);
                float m2 = s2 * (1.0f / 16.0f);
                m[i]  = mm;
                va[i] = fmaxf(m2 - mm * mm, 0.0f);
                xv[i] = S[(lb + i + HALO) * CT + tx];
            }
        }

        // ---------- conditioner MLP (exact-erf GELU) ----------
        float lg[RCHUNK][5];
        #pragma unroll
        for (int i = 0; i < RCHUNK; ++i)
            #pragma unroll
            for (int k = 0; k < 5; ++k) lg[i][k] = ws[288 + k];

        #pragma unroll 2
        for (int j = 0; j < 32; ++j) {
            float w1m = ws[j], w1v = ws[32 + j], w1x = ws[64 + j], bj = ws[96 + j];
            float w20 = ws[128 + j * 5 + 0];
            float w21 = ws[128 + j * 5 + 1];
            float w22 = ws[128 + j * 5 + 2];
            float w23 = ws[128 + j * 5 + 3];
            float w24 = ws[128 + j * 5 + 4];
            #pragma unroll
            for (int i = 0; i < RCHUNK; ++i) {
                float z = fmaf(m[i], w1m, fmaf(va[i], w1v, fmaf(xv[i], w1x, bj)));
                float g = 0.5f * z * (1.0f + erff(z * 0.70710678118654752f));
                lg[i][0] = fmaf(g, w20, lg[i][0]);
                lg[i][1] = fmaf(g, w21, lg[i][1]);
                lg[i][2] = fmaf(g, w22, lg[i][2]);
                lg[i][3] = fmaf(g, w23, lg[i][3]);
                lg[i][4] = fmaf(g, w24, lg[i][4]);
            }
        }

        // ---------- softmax over K, mix, store ----------
        float* op = out + ((size_t)bb * T + tb) * C + c0 + tx;
        #pragma unroll
        for (int i = 0; i < RCHUNK; ++i) {
            float mx = lg[i][0];
            #pragma unroll
            for (int k = 1; k < 5; ++k) mx = fmaxf(mx, lg[i][k]);
            float e0 = __expf(lg[i][0] - mx);
            float e1 = __expf(lg[i][1] - mx);
            float e2 = __expf(lg[i][2] - mx);
            float e3 = __expf(lg[i][3] - mx);
            float e4 = __expf(lg[i][4] - mx);
            float sum = e0 + e1 + e2 + e3 + e4;
            float dot = e0 * Y[i][0] + e1 * Y[i][1] + e2 * Y[i][2]
                      + e3 * Y[i][3] + e4 * Y[i][4];
            op[(size_t)i * C] = dot / sum;
        }
    }
}

// ---------------- launch ----------------
extern "C" void kernel_launch(void* const* d_in, const int* in_sizes, int n_in,
                              void* d_out, int out_size) {
    const float* x  = (const float*)d_in[0];
    const float* W1 = (const float*)d_in[1];
    const float* b1 = (const float*)d_in[2];
    const float* W2 = (const float*)d_in[3];
    const float* b2 = (const float*)d_in[4];
    float* out = (float*)d_out;

    const int B = 16, T = 4096, C = 256;
    size_t smem = (size_t)(ROWS * CT + 293) * sizeof(float);
    cudaFuncSetAttribute(agt_kernel, cudaFuncAttributeMaxDynamicSharedMemorySize, (int)smem);

    dim3 grid(C / CT, T / TT, B);
    dim3 block(CT, 2);
    agt_kernel<<<grid, block, smem>>>(x, W1, b1, W2, b2, out, B, T, C);
}

// round 4
// speedup vs baseline: 1.2717x; 1.2717x over previous
#include <cuda_runtime.h>
#include <math.h>

#define TT    64     // t-rows per block tile
#define CT    128    // channels per block tile
#define HALO  56     // max conv radius
#define ROWS  (TT + 2*HALO)   // 176
#define NTHREADS 256
#define RCHUNK 8     // outputs per thread per chunk
#define WSF   (ROWS * CT)     // float offset of duplicated weights in smem

typedef unsigned long long ull;

// ---------------- packed f32x2 helpers ----------------
__device__ __forceinline__ ull ffma2(ull a, ull b, ull c) {
    ull d; asm("fma.rn.f32x2 %0,%1,%2,%3;" : "=l"(d) : "l"(a), "l"(b), "l"(c)); return d;
}
__device__ __forceinline__ ull fmul2(ull a, ull b) {
    ull d; asm("mul.rn.f32x2 %0,%1,%2;" : "=l"(d) : "l"(a), "l"(b)); return d;
}
__device__ __forceinline__ ull pk2(float lo, float hi) {
    ull d; asm("mov.b64 %0,{%1,%2};" : "=l"(d) : "f"(lo), "f"(hi)); return d;
}
__device__ __forceinline__ void upk2(ull a, float& lo, float& hi) {
    asm("mov.b64 {%0,%1},%2;" : "=f"(lo), "=f"(hi) : "l"(a));
}
__device__ __forceinline__ ull abs2(ull a) {
    ull d; asm("and.b64 %0,%1,0x7FFFFFFF7FFFFFFF;" : "=l"(d) : "l"(a)); return d;
}
__device__ __forceinline__ ull neg2(ull a) {
    ull d; asm("xor.b64 %0,%1,0x8000000080000000;" : "=l"(d) : "l"(a)); return d;
}
__device__ __forceinline__ float rcpf(float x) {
    float r; asm("rcp.approx.f32 %0,%1;" : "=f"(r) : "f"(x)); return r;
}
__device__ __forceinline__ float ex2f(float x) {
    float r; asm("ex2.approx.f32 %0,%1;" : "=f"(r) : "f"(x)); return r;
}

// ---------------- compile-time Gaussian bank ----------------
__host__ __device__ constexpr double cexp_(double x) {
    double y = x / 256.0;
    double s = 1.0, term = 1.0;
    for (int n = 1; n <= 24; ++n) { term = term * y / (double)n; s += term; }
    for (int i = 0; i < 8; ++i) s = s * s;
    return s;
}

struct BankT { float w[5][113]; };

__host__ __device__ constexpr BankT make_bank() {
    BankT b{};
    double sig[5] = {2.5, 4.0, 6.0, 9.0, 14.0};
    for (int k = 0; k < 5; ++k) {
        double s = sig[k];
        int r = (int)(4.0 * s);          // 10,16,24,36,56
        double sum = 0.0;
        for (int d = -r; d <= r; ++d) sum += cexp_(-0.5 * ((double)d / s) * ((double)d / s));
        for (int d = -r; d <= r; ++d)
            b.w[k][56 + d] = (float)(cexp_(-0.5 * ((double)d / s) * ((double)d / s)) / sum);
    }
    return b;
}

// ---------------- kernel ----------------
__global__ void __launch_bounds__(NTHREADS, 2)
agt_kernel(const float* __restrict__ x, const float* __restrict__ W1,
           const float* __restrict__ b1, const float* __restrict__ W2,
           const float* __restrict__ b2, float* __restrict__ out,
           int B, int T, int C)
{
    constexpr BankT BANK = make_bank();
    constexpr int RAD[5] = {10, 16, 24, 36, 56};

    extern __shared__ float sm[];
    float* S   = sm;               // ROWS * CT tile
    float* ws2 = sm + WSF;         // duplicated weights: 586 floats

    const int tx  = threadIdx.x;
    const int ty  = threadIdx.y;
    const int tid = ty * CT + tx;
    const int c0  = blockIdx.x * CT;
    const int t0  = blockIdx.y * TT;
    const int bb  = blockIdx.z;

    // --- stage duplicated weights: flat order [W1(96)|b1(32)|W2(160)|b2(5)] ---
    for (int i = tid; i < 293; i += NTHREADS) {
        float v;
        if      (i <  96) v = W1[i];
        else if (i < 128) v = b1[i - 96];
        else if (i < 288) v = W2[i - 128];
        else              v = b2[i - 288];
        ws2[2 * i]     = v;
        ws2[2 * i + 1] = v;
    }

    // --- stage x tile (zero padded outside [0,T) for the conv) ---
    const float* xb = x + ((size_t)bb * T) * C + c0;
    for (int idx = tid; idx < ROWS * CT; idx += NTHREADS) {
        int r  = idx >> 7;
        int cc = idx & (CT - 1);
        int g  = t0 - HALO + r;
        float v = 0.0f;
        if (g >= 0 && g < T) v = xb[(size_t)g * C + cc];
        S[idx] = v;
    }
    __syncthreads();

    const float* Scol = S + tx;
    const ull*   wp   = (const ull*)ws2;   // pair index == flat weight index

    // packed constants (A&S 7.1.26 erf, x = |z|/sqrt(2))
    const ull CP    = pk2(0.23164190f,  0.23164190f);   // 0.3275911/sqrt(2)
    const ull CONE  = pk2(1.0f, 1.0f);
    const ull CEXP  = pk2(-0.72134752f, -0.72134752f);  // -0.5*log2(e)
    const ull CA5   = pk2( 1.061405429f,  1.061405429f);
    const ull CA4   = pk2(-1.453152027f, -1.453152027f);
    const ull CA3   = pk2( 1.421413741f,  1.421413741f);
    const ull CA2   = pk2(-0.284496736f, -0.284496736f);
    const ull CA1   = pk2( 0.254829592f,  0.254829592f);
    const ull CHALF = pk2(0.5f, 0.5f);
    const float LOG2E = 1.4426950408889634f;

    #pragma unroll 1
    for (int chunk = 0; chunk < TT / (2 * RCHUNK); ++chunk) {
        const int lb = ty * (TT / 2) + chunk * RCHUNK;  // local first output row (lb % 8 == 0)
        const int tb = t0 + lb;                         // global first output row
        const float* Sp = Scol + lb * CT;               // Sp[r*CT] = S[(lb+r)*CT+tx]

        // ---------- phase 1: mean / var over 16-window (reflect), plus x ----------
        float m[RCHUNK], va[RCHUNK], xv[RCHUNK];
        {
            float s = 0.0f, s2 = 0.0f;
            #pragma unroll
            for (int u = -7; u <= 8; ++u) {
                int g = tb + u;
                g = (g < 0)  ? -g              : g;
                g = (g >= T) ? (2 * T - 2 - g) : g;
                float w = Scol[(g - t0 + HALO) * CT];
                s += w; s2 += w * w;
            }
            #pragma unroll
            for (int i = 0; i < RCHUNK; ++i) {
                if (i > 0) {
                    int ga = tb + i + 8;  ga = (ga >= T) ? (2 * T - 2 - ga) : ga;
                    int gr = tb + i - 8;  gr = (gr < 0)  ? -gr              : gr;
                    float wa = Scol[(ga - t0 + HALO) * CT];
                    float wr = Scol[(gr - t0 + HALO) * CT];
                    s  += wa - wr;
                    s2 += wa * wa - wr * wr;
                }
                float mm = s  * (1.0f / 16.0f);
                float m2v = s2 * (1.0f / 16.0f);
                m[i]  = mm;
                va[i] = fmaxf(m2v - mm * mm, 0.0f);
                xv[i] = Sp[(HALO + i) * CT];
            }
        }

        // pack features into f32x2 pairs (i, i+1)
        ull m2[4], v2p[4], x2[4];
        #pragma unroll
        for (int p = 0; p < 4; ++p) {
            m2[p]  = pk2(m[2 * p],  m[2 * p + 1]);
            v2p[p] = pk2(va[2 * p], va[2 * p + 1]);
            x2[p]  = pk2(xv[2 * p], xv[2 * p + 1]);
        }

        // ---------- phase 2: conditioner MLP, fully packed, A&S erf GELU ----------
        ull lg[4][5];
        #pragma unroll
        for (int p = 0; p < 4; ++p)
            #pragma unroll
            for (int k = 0; k < 5; ++k) lg[p][k] = wp[288 + k];   // b2 pair

        #pragma unroll 2
        for (int j = 0; j < 32; ++j) {
            ull w1m = wp[j], w1v = wp[32 + j], w1x = wp[64 + j], bj = wp[96 + j];
            ull w20 = wp[128 + 5 * j + 0];
            ull w21 = wp[128 + 5 * j + 1];
            ull w22 = wp[128 + 5 * j + 2];
            ull w23 = wp[128 + 5 * j + 3];
            ull w24 = wp[128 + 5 * j + 4];
            #pragma unroll
            for (int p = 0; p < 4; ++p) {
                ull z  = ffma2(m2[p], w1m, ffma2(v2p[p], w1v, ffma2(x2[p], w1x, bj)));
                ull az = abs2(z);
                // t = 1/(1 + p'*|z|)
                ull dd = ffma2(az, CP, CONE);
                float dl, dh; upk2(dd, dl, dh);
                ull t = pk2(rcpf(dl), rcpf(dh));
                // e = exp(-z^2/2) via ex2
                ull zz = fmul2(z, z);
                ull ve = fmul2(zz, CEXP);
                float vl, vh; upk2(ve, vl, vh);
                ull e = pk2(ex2f(vl), ex2f(vh));
                // P(t) = t*(a1 + t*(a2 + t*(a3 + t*(a4 + t*a5))))
                ull P = ffma2(CA5, t, CA4);
                P = ffma2(P, t, CA3);
                P = ffma2(P, t, CA2);
                P = ffma2(P, t, CA1);
                P = fmul2(P, t);
                ull pe = fmul2(P, e);
                // gelu = 0.5*z + 0.5*|z| - 0.5*|z|*pe
                ull haz  = fmul2(az, CHALF);
                ull base = ffma2(z, CHALF, haz);
                ull g    = ffma2(neg2(haz), pe, base);
                lg[p][0] = ffma2(g, w20, lg[p][0]);
                lg[p][1] = ffma2(g, w21, lg[p][1]);
                lg[p][2] = ffma2(g, w22, lg[p][2]);
                lg[p][3] = ffma2(g, w23, lg[p][3]);
                lg[p][4] = ffma2(g, w24, lg[p][4]);
            }
        }

        // ---------- phase 3: softmax -> normalized mixture weights ----------
        float wgt[RCHUNK][5];
        #pragma unroll
        for (int p = 0; p < 4; ++p) {
            float lo[5], hi[5];
            #pragma unroll
            for (int k = 0; k < 5; ++k) upk2(lg[p][k], lo[k], hi[k]);
            {
                float e0 = ex2f(lo[0] * LOG2E), e1 = ex2f(lo[1] * LOG2E),
                      e2 = ex2f(lo[2] * LOG2E), e3 = ex2f(lo[3] * LOG2E),
                      e4 = ex2f(lo[4] * LOG2E);
                float r = rcpf(e0 + e1 + e2 + e3 + e4);
                wgt[2*p][0] = e0 * r; wgt[2*p][1] = e1 * r; wgt[2*p][2] = e2 * r;
                wgt[2*p][3] = e3 * r; wgt[2*p][4] = e4 * r;
            }
            {
                float e0 = ex2f(hi[0] * LOG2E), e1 = ex2f(hi[1] * LOG2E),
                      e2 = ex2f(hi[2] * LOG2E), e3 = ex2f(hi[3] * LOG2E),
                      e4 = ex2f(hi[4] * LOG2E);
                float r = rcpf(e0 + e1 + e2 + e3 + e4);
                wgt[2*p+1][0] = e0 * r; wgt[2*p+1][1] = e1 * r; wgt[2*p+1][2] = e2 * r;
                wgt[2*p+1][3] = e3 * r; wgt[2*p+1][4] = e4 * r;
            }
        }

        // ---------- phase 4: symmetric 5-sigma conv (ring-buffer windows) ----------
        float Y[RCHUNK][5];
        float Lb[8], Rb[8];
        #pragma unroll
        for (int o = 0; o < 8; ++o) {
            float vc = Sp[(HALO + o) * CT];   // slot (56+o)&7 == o
            Lb[o] = vc; Rb[o] = vc;
            #pragma unroll
            for (int k = 0; k < 5; ++k) Y[o][k] = vc * BANK.w[k][56];
        }
        #pragma unroll
        for (int d = 1; d <= 56; ++d) {
            Lb[(64 - d) & 7] = Sp[(HALO - d) * CT];
            Rb[(7 + d)  & 7] = Sp[(HALO + 7 + d) * CT];
            #pragma unroll
            for (int o = 0; o < 8; ++o) {
                float s = Lb[(64 + o - d) & 7] + Rb[(o + d) & 7];
                #pragma unroll
                for (int k = 0; k < 5; ++k) {
                    if (d <= RAD[k])
                        Y[o][k] = fmaf(s, BANK.w[k][56 + d], Y[o][k]);
                }
            }
        }

        // ---------- phase 5: mix + store ----------
        float* op = out + ((size_t)bb * T + tb) * C + c0 + tx;
        #pragma unroll
        for (int o = 0; o < 8; ++o) {
            float dot = Y[o][0] * wgt[o][0];
            dot = fmaf(Y[o][1], wgt[o][1], dot);
            dot = fmaf(Y[o][2], wgt[o][2], dot);
            dot = fmaf(Y[o][3], wgt[o][3], dot);
            dot = fmaf(Y[o][4], wgt[o][4], dot);
            op[(size_t)o * C] = dot;
        }
    }
}

// ---------------- launch ----------------
extern "C" void kernel_launch(void* const* d_in, const int* in_sizes, int n_in,
                              void* d_out, int out_size) {
    const float* x  = (const float*)d_in[0];
    const float* W1 = (const float*)d_in[1];
    const float* b1 = (const float*)d_in[2];
    const float* W2 = (const float*)d_in[3];
    const float* b2 = (const float*)d_in[4];
    float* out = (float*)d_out;

    const int B = 16, T = 4096, C = 256;
    size_t smem = (size_t)(WSF + 640) * sizeof(float);
    cudaFuncSetAttribute(agt_kernel, cudaFuncAttributeMaxDynamicSharedMemorySize, (int)smem);

    dim3 grid(C / CT, T / TT, B);
    dim3 block(CT, 2);
    agt_kernel<<<grid, block, smem>>>(x, W1, b1, W2, b2, out, B, T, C);
}

// round 5
// speedup vs baseline: 1.3709x; 1.0780x over previous
#include <cuda_runtime.h>
#include <math.h>

#define TT    64     // t-rows per block tile
#define CT    128    // channels per block tile
#define HALO  56     // max conv radius
#define ROWS  (TT + 2*HALO)   // 176
#define NTHREADS 256
#define RCHUNK 8     // outputs per thread per chunk
#define WSF   (ROWS * CT)     // float offset of duplicated weights in smem

typedef unsigned long long ull;

// ---------------- packed f32x2 helpers ----------------
__device__ __forceinline__ ull ffma2(ull a, ull b, ull c) {
    ull d; asm("fma.rn.f32x2 %0,%1,%2,%3;" : "=l"(d) : "l"(a), "l"(b), "l"(c)); return d;
}
__device__ __forceinline__ ull fmul2(ull a, ull b) {
    ull d; asm("mul.rn.f32x2 %0,%1,%2;" : "=l"(d) : "l"(a), "l"(b)); return d;
}
__device__ __forceinline__ ull pk2(float lo, float hi) {
    ull d; asm("mov.b64 %0,{%1,%2};" : "=l"(d) : "f"(lo), "f"(hi)); return d;
}
__device__ __forceinline__ void upk2(ull a, float& lo, float& hi) {
    asm("mov.b64 {%0,%1},%2;" : "=f"(lo), "=f"(hi) : "l"(a));
}
__device__ __forceinline__ ull abs2(ull a) {
    ull d; asm("and.b64 %0,%1,0x7FFFFFFF7FFFFFFF;" : "=l"(d) : "l"(a)); return d;
}
__device__ __forceinline__ float rcpf(float x) {
    float r; asm("rcp.approx.f32 %0,%1;" : "=f"(r) : "f"(x)); return r;
}
__device__ __forceinline__ float ex2f(float x) {
    float r; asm("ex2.approx.f32 %0,%1;" : "=f"(r) : "f"(x)); return r;
}

// ---------------- compile-time Gaussian bank ----------------
__host__ __device__ constexpr double cexp_(double x) {
    double y = x / 256.0;
    double s = 1.0, term = 1.0;
    for (int n = 1; n <= 24; ++n) { term = term * y / (double)n; s += term; }
    for (int i = 0; i < 8; ++i) s = s * s;
    return s;
}

struct BankT { float w[5][113]; };

__host__ __device__ constexpr BankT make_bank() {
    BankT b{};
    double sig[5] = {2.5, 4.0, 6.0, 9.0, 14.0};
    for (int k = 0; k < 5; ++k) {
        double s = sig[k];
        int r = (int)(4.0 * s);          // 10,16,24,36,56
        double sum = 0.0;
        for (int d = -r; d <= r; ++d) sum += cexp_(-0.5 * ((double)d / s) * ((double)d / s));
        for (int d = -r; d <= r; ++d)
            b.w[k][56 + d] = (float)(cexp_(-0.5 * ((double)d / s) * ((double)d / s)) / sum);
    }
    return b;
}

// ---------------- kernel ----------------
__global__ void __launch_bounds__(NTHREADS, 2)
agt_kernel(const float* __restrict__ x, const float* __restrict__ W1,
           const float* __restrict__ b1, const float* __restrict__ W2,
           const float* __restrict__ b2, float* __restrict__ out,
           int B, int T, int C)
{
    constexpr BankT BANK = make_bank();
    constexpr int RAD[5] = {10, 16, 24, 36, 56};
    const float LOG2E = 1.4426950408889634f;

    extern __shared__ float sm[];
    float* S   = sm;               // ROWS * CT tile
    float* ws2 = sm + WSF;         // duplicated weights: 586 floats

    const int tx  = threadIdx.x;
    const int ty  = threadIdx.y;
    const int tid = ty * CT + tx;
    const int c0  = blockIdx.x * CT;
    const int t0  = blockIdx.y * TT;
    const int bb  = blockIdx.z;

    // --- stage duplicated weights: [W1(96)|b1(32)|W2'(160)|b2'(5)] ---
    // W2' = W2 * 0.5 * log2(e)   (0.5 from GELU, log2e so softmax uses ex2 directly)
    // b2' = b2 * log2(e)
    for (int i = tid; i < 293; i += NTHREADS) {
        float v;
        if      (i <  96) v = W1[i];
        else if (i < 128) v = b1[i - 96];
        else if (i < 288) v = W2[i - 128] * (0.5f * 1.4426950408889634f);
        else              v = b2[i - 288] * 1.4426950408889634f;
        ws2[2 * i]     = v;
        ws2[2 * i + 1] = v;
    }

    // --- stage x tile (zero padded outside [0,T) for the conv) ---
    const float* xb = x + ((size_t)bb * T) * C + c0;
    for (int idx = tid; idx < ROWS * CT; idx += NTHREADS) {
        int r  = idx >> 7;
        int cc = idx & (CT - 1);
        int g  = t0 - HALO + r;
        float v = 0.0f;
        if (g >= 0 && g < T) v = xb[(size_t)g * C + cc];
        S[idx] = v;
    }
    __syncthreads();

    const float* Scol = S + tx;
    const ull*   wp   = (const ull*)ws2;   // pair index == flat weight index

    // packed constants: A&S 7.1.25 erf (3-term), x = |z|/sqrt(2)
    const ull CP    = pk2(0.33267720f,  0.33267720f);   // 0.47047/sqrt(2)
    const ull CONE  = pk2(1.0f, 1.0f);
    const ull CM1   = pk2(-1.0f, -1.0f);
    const ull CEXP  = pk2(-0.72134752f, -0.72134752f);  // -0.5*log2(e)
    const ull CA3   = pk2( 0.7478556f,  0.7478556f);
    const ull CA2   = pk2(-0.0958798f, -0.0958798f);
    const ull CA1   = pk2( 0.3480242f,  0.3480242f);

    const bool interior = (t0 >= 8) && (t0 + TT + 8 <= T);

    #pragma unroll 1
    for (int chunk = 0; chunk < TT / (2 * RCHUNK); ++chunk) {
        const int lb = ty * (TT / 2) + chunk * RCHUNK;  // local first output row
        const int tb = t0 + lb;                         // global first output row
        const float* Sp = Scol + lb * CT;               // Sp[r*CT] = S[(lb+r)*CT+tx]

        // ---------- phase 1: mean / var over 16-window, plus x ----------
        float m[RCHUNK], va[RCHUNK], xv[RCHUNK];
        if (interior) {
            float s = 0.0f, s2 = 0.0f;
            #pragma unroll
            for (int u = -7; u <= 8; ++u) {
                float w = Sp[(HALO + u) * CT];
                s += w; s2 += w * w;
            }
            #pragma unroll
            for (int i = 0; i < RCHUNK; ++i) {
                if (i > 0) {
                    float wa = Sp[(HALO + i + 8) * CT];
                    float wr = Sp[(HALO + i - 8) * CT];
                    s  += wa - wr;
                    s2 += wa * wa - wr * wr;
                }
                float mm  = s  * (1.0f / 16.0f);
                float m2v = s2 * (1.0f / 16.0f);
                m[i]  = mm;
                va[i] = fmaxf(m2v - mm * mm, 0.0f);
                xv[i] = Sp[(HALO + i) * CT];
            }
        } else {
            float s = 0.0f, s2 = 0.0f;
            #pragma unroll
            for (int u = -7; u <= 8; ++u) {
                int g = tb + u;
                g = (g < 0)  ? -g              : g;
                g = (g >= T) ? (2 * T - 2 - g) : g;
                float w = Scol[(g - t0 + HALO) * CT];
                s += w; s2 += w * w;
            }
            #pragma unroll
            for (int i = 0; i < RCHUNK; ++i) {
                if (i > 0) {
                    int ga = tb + i + 8;  ga = (ga >= T) ? (2 * T - 2 - ga) : ga;
                    int gr = tb + i - 8;  gr = (gr < 0)  ? -gr              : gr;
                    float wa = Scol[(ga - t0 + HALO) * CT];
                    float wr = Scol[(gr - t0 + HALO) * CT];
                    s  += wa - wr;
                    s2 += wa * wa - wr * wr;
                }
                float mm  = s  * (1.0f / 16.0f);
                float m2v = s2 * (1.0f / 16.0f);
                m[i]  = mm;
                va[i] = fmaxf(m2v - mm * mm, 0.0f);
                xv[i] = Sp[(HALO + i) * CT];
            }
        }

        // pack features into f32x2 pairs (i, i+1)
        ull m2[4], v2p[4], x2[4];
        #pragma unroll
        for (int p = 0; p < 4; ++p) {
            m2[p]  = pk2(m[2 * p],  m[2 * p + 1]);
            v2p[p] = pk2(va[2 * p], va[2 * p + 1]);
            x2[p]  = pk2(xv[2 * p], xv[2 * p + 1]);
        }

        // ---------- phase 2: conditioner MLP, packed, A&S 7.1.25 erf GELU ----------
        // lg accumulates log2e * logits;  g' = 2*gelu = z + |z|*(1 - P(t)e^{-z^2/2})
        ull lg[4][5];
        #pragma unroll
        for (int p = 0; p < 4; ++p)
            #pragma unroll
            for (int k = 0; k < 5; ++k) lg[p][k] = wp[288 + k];   // b2' pair

        #pragma unroll 2
        for (int j = 0; j < 32; ++j) {
            ull w1m = wp[j], w1v = wp[32 + j], w1x = wp[64 + j], bj = wp[96 + j];
            ull w20 = wp[128 + 5 * j + 0];
            ull w21 = wp[128 + 5 * j + 1];
            ull w22 = wp[128 + 5 * j + 2];
            ull w23 = wp[128 + 5 * j + 3];
            ull w24 = wp[128 + 5 * j + 4];
            #pragma unroll
            for (int p = 0; p < 4; ++p) {
                ull z  = ffma2(m2[p], w1m, ffma2(v2p[p], w1v, ffma2(x2[p], w1x, bj)));
                ull az = abs2(z);
                // t = 1/(1 + p'*|z|)
                ull dd = ffma2(az, CP, CONE);
                float dl, dh; upk2(dd, dl, dh);
                ull t = pk2(rcpf(dl), rcpf(dh));
                // e = exp(-z^2/2) via ex2
                ull zz = fmul2(z, z);
                ull ve = fmul2(zz, CEXP);
                float vl, vh; upk2(ve, vl, vh);
                ull e = pk2(ex2f(vl), ex2f(vh));
                // P(t) = t*(a1 + t*(a2 + t*a3))
                ull P = ffma2(CA3, t, CA2);
                P = ffma2(P, t, CA1);
                P = fmul2(P, t);
                ull pe = fmul2(P, e);
                // g' = z + |z|*(1 - pe)
                ull u = ffma2(pe, CM1, CONE);
                ull g = ffma2(az, u, z);
                lg[p][0] = ffma2(g, w20, lg[p][0]);
                lg[p][1] = ffma2(g, w21, lg[p][1]);
                lg[p][2] = ffma2(g, w22, lg[p][2]);
                lg[p][3] = ffma2(g, w23, lg[p][3]);
                lg[p][4] = ffma2(g, w24, lg[p][4]);
            }
        }

        // ---------- phase 3: symmetric 5-sigma conv (ring-buffer windows) ----------
        float Y[RCHUNK][5];
        float Lb[8], Rb[8];
        #pragma unroll
        for (int o = 0; o < 8; ++o) {
            float vc = Sp[(HALO + o) * CT];   // slot (56+o)&7 == o
            Lb[o] = vc; Rb[o] = vc;
            #pragma unroll
            for (int k = 0; k < 5; ++k) Y[o][k] = vc * BANK.w[k][56];
        }
        #pragma unroll
        for (int d = 1; d <= 56; ++d) {
            Lb[(64 - d) & 7] = Sp[(HALO - d) * CT];
            Rb[(7 + d)  & 7] = Sp[(HALO + 7 + d) * CT];
            #pragma unroll
            for (int o = 0; o < 8; ++o) {
                float s = Lb[(64 + o - d) & 7] + Rb[(o + d) & 7];
                #pragma unroll
                for (int k = 0; k < 5; ++k) {
                    if (d <= RAD[k])
                        Y[o][k] = fmaf(s, BANK.w[k][56 + d], Y[o][k]);
                }
            }
        }

        // ---------- phase 4: softmax (unnormalized) + mix + store ----------
        float* op = out + ((size_t)bb * T + tb) * C + c0 + tx;
        #pragma unroll
        for (int p = 0; p < 4; ++p) {
            float lo[5], hi[5];
            #pragma unroll
            for (int k = 0; k < 5; ++k) upk2(lg[p][k], lo[k], hi[k]);
            {
                const int o = 2 * p;
                float e0 = ex2f(lo[0]), e1 = ex2f(lo[1]), e2 = ex2f(lo[2]),
                      e3 = ex2f(lo[3]), e4 = ex2f(lo[4]);
                float sum = ((e0 + e1) + (e2 + e3)) + e4;
                float dot = e0 * Y[o][0];
                dot = fmaf(e1, Y[o][1], dot);
                dot = fmaf(e2, Y[o][2], dot);
                dot = fmaf(e3, Y[o][3], dot);
                dot = fmaf(e4, Y[o][4], dot);
                op[(size_t)o * C] = dot * rcpf(sum);
            }
            {
                const int o = 2 * p + 1;
                float e0 = ex2f(hi[0]), e1 = ex2f(hi[1]), e2 = ex2f(hi[2]),
                      e3 = ex2f(hi[3]), e4 = ex2f(hi[4]);
                float sum = ((e0 + e1) + (e2 + e3)) + e4;
                float dot = e0 * Y[o][0];
                dot = fmaf(e1, Y[o][1], dot);
                dot = fmaf(e2, Y[o][2], dot);
                dot = fmaf(e3, Y[o][3], dot);
                dot = fmaf(e4, Y[o][4], dot);
                op[(size_t)o * C] = dot * rcpf(sum);
            }
        }
    }
}

// ---------------- launch ----------------
extern "C" void kernel_launch(void* const* d_in, const int* in_sizes, int n_in,
                              void* d_out, int out_size) {
    const float* x  = (const float*)d_in[0];
    const float* W1 = (const float*)d_in[1];
    const float* b1 = (const float*)d_in[2];
    const float* W2 = (const float*)d_in[3];
    const float* b2 = (const float*)d_in[4];
    float* out = (float*)d_out;

    const int B = 16, T = 4096, C = 256;
    size_t smem = (size_t)(WSF + 640) * sizeof(float);
    cudaFuncSetAttribute(agt_kernel, cudaFuncAttributeMaxDynamicSharedMemorySize, (int)smem);

    dim3 grid(C / CT, T / TT, B);
    dim3 block(CT, 2);
    agt_kernel<<<grid, block, smem>>>(x, W1, b1, W2, b2, out, B, T, C);
}

// round 6
// speedup vs baseline: 1.5765x; 1.1500x over previous
#include <cuda_runtime.h>
#include <math.h>

#define TT    64     // t-rows per block tile
#define CT    128    // channels per block tile
#define HALO  56     // max conv radius
#define ROWS  (TT + 2*HALO)   // 176
#define NTHREADS 256
#define RCHUNK 8     // outputs per thread per chunk
#define WSF   (ROWS * CT)     // float offset of duplicated weights in smem

typedef unsigned long long ull;

// ---------------- packed f32x2 helpers ----------------
__device__ __forceinline__ ull ffma2(ull a, ull b, ull c) {
    ull d; asm("fma.rn.f32x2 %0,%1,%2,%3;" : "=l"(d) : "l"(a), "l"(b), "l"(c)); return d;
}
__device__ __forceinline__ ull fmul2(ull a, ull b) {
    ull d; asm("mul.rn.f32x2 %0,%1,%2;" : "=l"(d) : "l"(a), "l"(b)); return d;
}
__device__ __forceinline__ ull pk2(float lo, float hi) {
    ull d; asm("mov.b64 %0,{%1,%2};" : "=l"(d) : "f"(lo), "f"(hi)); return d;
}
__device__ __forceinline__ void upk2(ull a, float& lo, float& hi) {
    asm("mov.b64 {%0,%1},%2;" : "=f"(lo), "=f"(hi) : "l"(a));
}
__device__ __forceinline__ float rcpf(float x) {
    float r; asm("rcp.approx.f32 %0,%1;" : "=f"(r) : "f"(x)); return r;
}
__device__ __forceinline__ float ex2f(float x) {
    float r; asm("ex2.approx.f32 %0,%1;" : "=f"(r) : "f"(x)); return r;
}

// ---------------- compile-time Gaussian bank ----------------
__host__ __device__ constexpr double cexp_(double x) {
    double y = x / 256.0;
    double s = 1.0, term = 1.0;
    for (int n = 1; n <= 24; ++n) { term = term * y / (double)n; s += term; }
    for (int i = 0; i < 8; ++i) s = s * s;
    return s;
}

struct BankT { float w[5][113]; };

__host__ __device__ constexpr BankT make_bank() {
    BankT b{};
    double sig[5] = {2.5, 4.0, 6.0, 9.0, 14.0};
    for (int k = 0; k < 5; ++k) {
        double s = sig[k];
        int r = (int)(4.0 * s);          // 10,16,24,36,56
        double sum = 0.0;
        for (int d = -r; d <= r; ++d) sum += cexp_(-0.5 * ((double)d / s) * ((double)d / s));
        for (int d = -r; d <= r; ++d)
            b.w[k][56 + d] = (float)(cexp_(-0.5 * ((double)d / s) * ((double)d / s)) / sum);
    }
    return b;
}

// ---------------- kernel ----------------
__global__ void __launch_bounds__(NTHREADS, 2)
agt_kernel(const float* __restrict__ x, const float* __restrict__ W1,
           const float* __restrict__ b1, const float* __restrict__ W2,
           const float* __restrict__ b2, float* __restrict__ out,
           int B, int T, int C)
{
    constexpr BankT BANK = make_bank();
    constexpr int RAD[5] = {10, 16, 24, 36, 56};

    extern __shared__ float sm[];
    float* S   = sm;               // ROWS * CT tile
    float* ws2 = sm + WSF;         // duplicated weights: 586 floats

    const int tx  = threadIdx.x;
    const int ty  = threadIdx.y;
    const int tid = ty * CT + tx;
    const int c0  = blockIdx.x * CT;
    const int t0  = blockIdx.y * TT;
    const int bb  = blockIdx.z;

    // --- stage duplicated weights: [W1(96)|b1(32)|W2'(160)|b2'(5)] ---
    // W2' = W2 * log2(e), b2' = b2 * log2(e): lg accumulates log2e*logits so
    // softmax uses ex2 directly. (tanh-GELU: g = z*sigmoid(2u) = gelu exactly.)
    for (int i = tid; i < 293; i += NTHREADS) {
        float v;
        if      (i <  96) v = W1[i];
        else if (i < 128) v = b1[i - 96];
        else if (i < 288) v = W2[i - 128] * 1.4426950408889634f;
        else              v = b2[i - 288] * 1.4426950408889634f;
        ws2[2 * i]     = v;
        ws2[2 * i + 1] = v;
    }

    // --- stage x tile (zero padded outside [0,T) for the conv) ---
    const float* xb = x + ((size_t)bb * T) * C + c0;
    for (int idx = tid; idx < ROWS * CT; idx += NTHREADS) {
        int r  = idx >> 7;
        int cc = idx & (CT - 1);
        int g  = t0 - HALO + r;
        float v = 0.0f;
        if (g >= 0 && g < T) v = xb[(size_t)g * C + cc];
        S[idx] = v;
    }
    __syncthreads();

    const float* Scol = S + tx;
    const ull*   wp   = (const ull*)ws2;   // pair index == flat weight index

    // tanh-GELU constants: ve = z*(C1 + C2*z^2) = -2*log2(e)*sqrt(2/pi)*(z + 0.044715 z^3)
    const ull CC1 = pk2(-2.302211926f, -2.302211926f);
    const ull CC2 = pk2(-0.102943414f, -0.102943414f);

    const bool interior = (t0 >= 8) && (t0 + TT + 8 <= T);

    #pragma unroll 1
    for (int chunk = 0; chunk < TT / (2 * RCHUNK); ++chunk) {
        const int lb = ty * (TT / 2) + chunk * RCHUNK;  // local first output row
        const int tb = t0 + lb;                         // global first output row
        const float* Sp = Scol + lb * CT;               // Sp[r*CT] = S[(lb+r)*CT+tx]

        // ---------- phase 1: mean / var over 16-window, plus x ----------
        float m[RCHUNK], va[RCHUNK], xv[RCHUNK];
        if (interior) {
            float s = 0.0f, s2 = 0.0f;
            #pragma unroll
            for (int u = -7; u <= 8; ++u) {
                float w = Sp[(HALO + u) * CT];
                s += w; s2 += w * w;
            }
            #pragma unroll
            for (int i = 0; i < RCHUNK; ++i) {
                if (i > 0) {
                    float wa = Sp[(HALO + i + 8) * CT];
                    float wr = Sp[(HALO + i - 8) * CT];
                    s  += wa - wr;
                    s2 += wa * wa - wr * wr;
                }
                float mm  = s  * (1.0f / 16.0f);
                float m2v = s2 * (1.0f / 16.0f);
                m[i]  = mm;
                va[i] = fmaxf(m2v - mm * mm, 0.0f);
                xv[i] = Sp[(HALO + i) * CT];
            }
        } else {
            float s = 0.0f, s2 = 0.0f;
            #pragma unroll
            for (int u = -7; u <= 8; ++u) {
                int g = tb + u;
                g = (g < 0)  ? -g              : g;
                g = (g >= T) ? (2 * T - 2 - g) : g;
                float w = Scol[(g - t0 + HALO) * CT];
                s += w; s2 += w * w;
            }
            #pragma unroll
            for (int i = 0; i < RCHUNK; ++i) {
                if (i > 0) {
                    int ga = tb + i + 8;  ga = (ga >= T) ? (2 * T - 2 - ga) : ga;
                    int gr = tb + i - 8;  gr = (gr < 0)  ? -gr              : gr;
                    float wa = Scol[(ga - t0 + HALO) * CT];
                    float wr = Scol[(gr - t0 + HALO) * CT];
                    s  += wa - wr;
                    s2 += wa * wa - wr * wr;
                }
                float mm  = s  * (1.0f / 16.0f);
                float m2v = s2 * (1.0f / 16.0f);
                m[i]  = mm;
                va[i] = fmaxf(m2v - mm * mm, 0.0f);
                xv[i] = Sp[(HALO + i) * CT];
            }
        }

        // pack features into f32x2 pairs (i, i+1)
        ull m2[4], v2p[4], x2[4];
        #pragma unroll
        for (int p = 0; p < 4; ++p) {
            m2[p]  = pk2(m[2 * p],  m[2 * p + 1]);
            v2p[p] = pk2(va[2 * p], va[2 * p + 1]);
            x2[p]  = pk2(xv[2 * p], xv[2 * p + 1]);
        }

        // ---------- phase 2: conditioner MLP, packed tanh-GELU ----------
        // g = z * sigmoid(2u) = z / (1 + 2^ve);  one rcp per pair via
        // r = 1/(d_lo*d_hi), t_lo = r*d_hi, t_hi = r*d_lo.
        ull lg[4][5];
        #pragma unroll
        for (int p = 0; p < 4; ++p)
            #pragma unroll
            for (int k = 0; k < 5; ++k) lg[p][k] = wp[288 + k];   // b2' pair

        #pragma unroll 2
        for (int j = 0; j < 32; ++j) {
            ull w1m = wp[j], w1v = wp[32 + j], w1x = wp[64 + j], bj = wp[96 + j];
            ull w20 = wp[128 + 5 * j + 0];
            ull w21 = wp[128 + 5 * j + 1];
            ull w22 = wp[128 + 5 * j + 2];
            ull w23 = wp[128 + 5 * j + 3];
            ull w24 = wp[128 + 5 * j + 4];
            #pragma unroll
            for (int p = 0; p < 4; ++p) {
                ull z  = ffma2(m2[p], w1m, ffma2(v2p[p], w1v, ffma2(x2[p], w1x, bj)));
                ull zz = fmul2(z, z);
                ull ve = fmul2(z, ffma2(zz, CC2, CC1));
                float vl, vh; upk2(ve, vl, vh);
                float dl = ex2f(vl) + 1.0f;
                float dh = ex2f(vh) + 1.0f;
                float r  = rcpf(dl * dh);
                ull t = pk2(r * dh, r * dl);
                ull g = fmul2(z, t);
                lg[p][0] = ffma2(g, w20, lg[p][0]);
                lg[p][1] = ffma2(g, w21, lg[p][1]);
                lg[p][2] = ffma2(g, w22, lg[p][2]);
                lg[p][3] = ffma2(g, w23, lg[p][3]);
                lg[p][4] = ffma2(g, w24, lg[p][4]);
            }
        }

        // ---------- phase 3: symmetric 5-sigma conv (ring-buffer windows) ----------
        float Y[RCHUNK][5];
        float Lb[8], Rb[8];
        #pragma unroll
        for (int o = 0; o < 8; ++o) {
            float vc = Sp[(HALO + o) * CT];   // slot (56+o)&7 == o
            Lb[o] = vc; Rb[o] = vc;
            #pragma unroll
            for (int k = 0; k < 5; ++k) Y[o][k] = vc * BANK.w[k][56];
        }
        #pragma unroll
        for (int d = 1; d <= 56; ++d) {
            Lb[(64 - d) & 7] = Sp[(HALO - d) * CT];
            Rb[(7 + d)  & 7] = Sp[(HALO + 7 + d) * CT];
            #pragma unroll
            for (int o = 0; o < 8; ++o) {
                float Lv = Lb[(64 + o - d) & 7];
                float Rv = Rb[(o + d) & 7];
                if (d > RAD[1]) {
                    // only sigma tails active: two FFMA-imm beat FADD+FFMA
                    #pragma unroll
                    for (int k = 0; k < 5; ++k) {
                        if (d <= RAD[k]) {
                            Y[o][k] = fmaf(Lv, BANK.w[k][56 + d], Y[o][k]);
                            Y[o][k] = fmaf(Rv, BANK.w[k][56 + d], Y[o][k]);
                        }
                    }
                } else {
                    float s = Lv + Rv;
                    #pragma unroll
                    for (int k = 0; k < 5; ++k) {
                        if (d <= RAD[k])
                            Y[o][k] = fmaf(s, BANK.w[k][56 + d], Y[o][k]);
                    }
                }
            }
        }

        // ---------- phase 4: softmax (unnormalized) + mix + store ----------
        float* op = out + ((size_t)bb * T + tb) * C + c0 + tx;
        #pragma unroll
        for (int p = 0; p < 4; ++p) {
            float lo[5], hi[5];
            #pragma unroll
            for (int k = 0; k < 5; ++k) upk2(lg[p][k], lo[k], hi[k]);
            {
                const int o = 2 * p;
                float e0 = ex2f(lo[0]), e1 = ex2f(lo[1]), e2 = ex2f(lo[2]),
                      e3 = ex2f(lo[3]), e4 = ex2f(lo[4]);
                float sum = ((e0 + e1) + (e2 + e3)) + e4;
                float dot = e0 * Y[o][0];
                dot = fmaf(e1, Y[o][1], dot);
                dot = fmaf(e2, Y[o][2], dot);
                dot = fmaf(e3, Y[o][3], dot);
                dot = fmaf(e4, Y[o][4], dot);
                op[(size_t)o * C] = dot * rcpf(sum);
            }
            {
                const int o = 2 * p + 1;
                float e0 = ex2f(hi[0]), e1 = ex2f(hi[1]), e2 = ex2f(hi[2]),
                      e3 = ex2f(hi[3]), e4 = ex2f(hi[4]);
                float sum = ((e0 + e1) + (e2 + e3)) + e4;
                float dot = e0 * Y[o][0];
                dot = fmaf(e1, Y[o][1], dot);
                dot = fmaf(e2, Y[o][2], dot);
                dot = fmaf(e3, Y[o][3], dot);
                dot = fmaf(e4, Y[o][4], dot);
                op[(size_t)o * C] = dot * rcpf(sum);
            }
        }
    }
}

// ---------------- launch ----------------
extern "C" void kernel_launch(void* const* d_in, const int* in_sizes, int n_in,
                              void* d_out, int out_size) {
    const float* x  = (const float*)d_in[0];
    const float* W1 = (const float*)d_in[1];
    const float* b1 = (const float*)d_in[2];
    const float* W2 = (const float*)d_in[3];
    const float* b2 = (const float*)d_in[4];
    float* out = (float*)d_out;

    const int B = 16, T = 4096, C = 256;
    size_t smem = (size_t)(WSF + 640) * sizeof(float);
    cudaFuncSetAttribute(agt_kernel, cudaFuncAttributeMaxDynamicSharedMemorySize, (int)smem);

    dim3 grid(C / CT, T / TT, B);
    dim3 block(CT, 2);
    agt_kernel<<<grid, block, smem>>>(x, W1, b1, W2, b2, out, B, T, C);
}

// round 8
// speedup vs baseline: 2.0019x; 1.2699x over previous
#include <cuda_runtime.h>
#include <math.h>

#define TT    64     // t-rows per block tile
#define CT    128    // channels per block tile
#define HALO  56     // max conv radius
#define ROWS  (TT + 2*HALO)   // 176
#define NTHREADS 256
#define RCHUNK 8     // outputs per thread per chunk
#define WSF   (ROWS * CT)     // float offset of duplicated weights in smem

typedef unsigned long long ull;

// ---------------- packed f32x2 helpers ----------------
__device__ __forceinline__ ull ffma2(ull a, ull b, ull c) {
    ull d; asm("fma.rn.f32x2 %0,%1,%2,%3;" : "=l"(d) : "l"(a), "l"(b), "l"(c)); return d;
}
__device__ __forceinline__ ull fmul2(ull a, ull b) {
    ull d; asm("mul.rn.f32x2 %0,%1,%2;" : "=l"(d) : "l"(a), "l"(b)); return d;
}
__device__ __forceinline__ ull pk2(float lo, float hi) {
    ull d; asm("mov.b64 %0,{%1,%2};" : "=l"(d) : "f"(lo), "f"(hi)); return d;
}
__device__ __forceinline__ void upk2(ull a, float& lo, float& hi) {
    asm("mov.b64 {%0,%1},%2;" : "=f"(lo), "=f"(hi) : "l"(a));
}
__device__ __forceinline__ float rcpf(float x) {
    float r; asm("rcp.approx.f32 %0,%1;" : "=f"(r) : "f"(x)); return r;
}
__device__ __forceinline__ float ex2f(float x) {
    float r; asm("ex2.approx.f32 %0,%1;" : "=f"(r) : "f"(x)); return r;
}
__device__ __forceinline__ float tanhf_a(float x) {
    float r; asm("tanh.approx.f32 %0,%1;" : "=f"(r) : "f"(x)); return r;
}

// ---------------- compile-time Gaussian bank ----------------
__host__ __device__ constexpr double cexp_(double x) {
    double y = x / 256.0;
    double s = 1.0, term = 1.0;
    for (int n = 1; n <= 24; ++n) { term = term * y / (double)n; s += term; }
    for (int i = 0; i < 8; ++i) s = s * s;
    return s;
}

struct BankT { float w[5][113]; };

__host__ __device__ constexpr BankT make_bank() {
    BankT b{};
    double sig[5] = {2.5, 4.0, 6.0, 9.0, 14.0};
    for (int k = 0; k < 5; ++k) {
        double s = sig[k];
        int r = (int)(4.0 * s);          // 10,16,24,36,56
        double sum = 0.0;
        for (int d = -r; d <= r; ++d) sum += cexp_(-0.5 * ((double)d / s) * ((double)d / s));
        for (int d = -r; d <= r; ++d)
            b.w[k][56 + d] = (float)(cexp_(-0.5 * ((double)d / s) * ((double)d / s)) / sum);
    }
    return b;
}

// ---------------- kernel ----------------
__global__ void __launch_bounds__(NTHREADS, 2)
agt_kernel(const float* __restrict__ x, const float* __restrict__ W1,
           const float* __restrict__ b1, const float* __restrict__ W2,
           const float* __restrict__ b2, float* __restrict__ out,
           int B, int T, int C)
{
    constexpr BankT BANK = make_bank();
    constexpr int RAD[5] = {10, 16, 24, 36, 56};

    extern __shared__ float sm[];
    float* S   = sm;               // ROWS * CT tile
    float* ws2 = sm + WSF;         // duplicated weights: 586 floats

    const int tx  = threadIdx.x;
    const int ty  = threadIdx.y;
    const int tid = ty * CT + tx;
    const int c0  = blockIdx.x * CT;
    const int t0  = blockIdx.y * TT;
    const int bb  = blockIdx.z;

    // --- stage duplicated weights: [W1(96)|b1(32)|W2'(160)|b2'(5)] ---
    // tanh-GELU: gelu = 0.5*z*(1+tanh(u)); fold 0.5*log2(e) into W2', log2(e)
    // into b2' so lg accumulates log2e*logits (softmax uses ex2 directly) and
    // the MLP computes g' = z + z*tanh(u) = 2*gelu.
    for (int i = tid; i < 293; i += NTHREADS) {
        float v;
        if      (i <  96) v = W1[i];
        else if (i < 128) v = b1[i - 96];
        else if (i < 288) v = W2[i - 128] * (0.5f * 1.4426950408889634f);
        else              v = b2[i - 288] * 1.4426950408889634f;
        ws2[2 * i]     = v;
        ws2[2 * i + 1] = v;
    }

    // --- stage x tile (zero padded outside [0,T) for the conv) ---
    const float* xb = x + ((size_t)bb * T) * C + c0;
    for (int idx = tid; idx < ROWS * CT; idx += NTHREADS) {
        int r  = idx >> 7;
        int cc = idx & (CT - 1);
        int g  = t0 - HALO + r;
        float v = 0.0f;
        if (g >= 0 && g < T) v = xb[(size_t)g * C + cc];
        S[idx] = v;
    }
    __syncthreads();

    const float* Scol = S + tx;
    const ull*   wp   = (const ull*)ws2;   // pair index == flat weight index

    // tanh-GELU: u = z*(CT1 + CT2*z^2), CT1=sqrt(2/pi), CT2=sqrt(2/pi)*0.044715
    const ull CT1 = pk2(0.7978845608f, 0.7978845608f);
    const ull CT2 = pk2(0.0356774081f, 0.0356774081f);

    const bool interior = (t0 >= 8) && (t0 + TT + 8 <= T);

    #pragma unroll 1
    for (int chunk = 0; chunk < TT / (2 * RCHUNK); ++chunk) {
        const int lb = ty * (TT / 2) + chunk * RCHUNK;  // local first output row
        const int tb = t0 + lb;                         // global first output row
        const float* Sp = Scol + lb * CT;               // Sp[r*CT] = S[(lb+r)*CT+tx]

        // ---------- phase 1: mean / var over 16-window, plus x ----------
        float m[RCHUNK], va[RCHUNK], xv[RCHUNK];
        if (interior) {
            float s = 0.0f, s2 = 0.0f;
            #pragma unroll
            for (int u = -7; u <= 8; ++u) {
                float w = Sp[(HALO + u) * CT];
                s += w; s2 += w * w;
            }
            #pragma unroll
            for (int i = 0; i < RCHUNK; ++i) {
                if (i > 0) {
                    float wa = Sp[(HALO + i + 8) * CT];
                    float wr = Sp[(HALO + i - 8) * CT];
                    s  += wa - wr;
                    s2 += wa * wa - wr * wr;
                }
                float mm  = s  * (1.0f / 16.0f);
                float m2v = s2 * (1.0f / 16.0f);
                m[i]  = mm;
                va[i] = fmaxf(m2v - mm * mm, 0.0f);
                xv[i] = Sp[(HALO + i) * CT];
            }
        } else {
            float s = 0.0f, s2 = 0.0f;
            #pragma unroll
            for (int u = -7; u <= 8; ++u) {
                int g = tb + u;
                g = (g < 0)  ? -g              : g;
                g = (g >= T) ? (2 * T - 2 - g) : g;
                float w = Scol[(g - t0 + HALO) * CT];
                s += w; s2 += w * w;
            }
            #pragma unroll
            for (int i = 0; i < RCHUNK; ++i) {
                if (i > 0) {
                    int ga = tb + i + 8;  ga = (ga >= T) ? (2 * T - 2 - ga) : ga;
                    int gr = tb + i - 8;  gr = (gr < 0)  ? -gr              : gr;
                    float wa = Scol[(ga - t0 + HALO) * CT];
                    float wr = Scol[(gr - t0 + HALO) * CT];
                    s  += wa - wr;
                    s2 += wa * wa - wr * wr;
                }
                float mm  = s  * (1.0f / 16.0f);
                float m2v = s2 * (1.0f / 16.0f);
                m[i]  = mm;
                va[i] = fmaxf(m2v - mm * mm, 0.0f);
                xv[i] = Sp[(HALO + i) * CT];
            }
        }

        // pack features into f32x2 pairs (i, i+1)
        ull m2[4], v2p[4], x2[4];
        #pragma unroll
        for (int p = 0; p < 4; ++p) {
            m2[p]  = pk2(m[2 * p],  m[2 * p + 1]);
            v2p[p] = pk2(va[2 * p], va[2 * p + 1]);
            x2[p]  = pk2(xv[2 * p], xv[2 * p + 1]);
        }

        // ---------- phase 2: conditioner MLP, packed tanh.approx GELU ----------
        ull lg[4][5];
        #pragma unroll
        for (int p = 0; p < 4; ++p)
            #pragma unroll
            for (int k = 0; k < 5; ++k) lg[p][k] = wp[288 + k];   // b2' pair

        #pragma unroll 2
        for (int j = 0; j < 32; ++j) {
            ull w1m = wp[j], w1v = wp[32 + j], w1x = wp[64 + j], bj = wp[96 + j];
            ull w20 = wp[128 + 5 * j + 0];
            ull w21 = wp[128 + 5 * j + 1];
            ull w22 = wp[128 + 5 * j + 2];
            ull w23 = wp[128 + 5 * j + 3];
            ull w24 = wp[128 + 5 * j + 4];
            #pragma unroll
            for (int p = 0; p < 4; ++p) {
                ull z  = ffma2(m2[p], w1m, ffma2(v2p[p], w1v, ffma2(x2[p], w1x, bj)));
                ull zz = fmul2(z, z);
                ull u  = fmul2(z, ffma2(zz, CT2, CT1));
                float ul, uh; upk2(u, ul, uh);
                ull th = pk2(tanhf_a(ul), tanhf_a(uh));
                ull g  = ffma2(z, th, z);        // g' = z*(1 + tanh(u)) = 2*gelu
                lg[p][0] = ffma2(g, w20, lg[p][0]);
                lg[p][1] = ffma2(g, w21, lg[p][1]);
                lg[p][2] = ffma2(g, w22, lg[p][2]);
                lg[p][3] = ffma2(g, w23, lg[p][3]);
                lg[p][4] = ffma2(g, w24, lg[p][4]);
            }
        }

        // ---------- phase 3: symmetric 5-sigma conv (ring-buffer windows) ----------
        float Y[RCHUNK][5];
        float Lb[8], Rb[8];
        #pragma unroll
        for (int o = 0; o < 8; ++o) {
            float vc = Sp[(HALO + o) * CT];   // slot (56+o)&7 == o
            Lb[o] = vc; Rb[o] = vc;
            #pragma unroll
            for (int k = 0; k < 5; ++k) Y[o][k] = vc * BANK.w[k][56];
        }
        #pragma unroll
        for (int d = 1; d <= 56; ++d) {
            Lb[(64 - d) & 7] = Sp[(HALO - d) * CT];
            Rb[(7 + d)  & 7] = Sp[(HALO + 7 + d) * CT];
            #pragma unroll
            for (int o = 0; o < 8; ++o) {
                float Lv = Lb[(64 + o - d) & 7];
                float Rv = Rb[(o + d) & 7];
                if (d > RAD[1]) {
                    // only sigma tails active: two FFMA-imm beat FADD+FFMA
                    #pragma unroll
                    for (int k = 0; k < 5; ++k) {
                        if (d <= RAD[k]) {
                            Y[o][k] = fmaf(Lv, BANK.w[k][56 + d], Y[o][k]);
                            Y[o][k] = fmaf(Rv, BANK.w[k][56 + d], Y[o][k]);
                        }
                    }
                } else {
                    float s = Lv + Rv;
                    #pragma unroll
                    for (int k = 0; k < 5; ++k) {
                        if (d <= RAD[k])
                            Y[o][k] = fmaf(s, BANK.w[k][56 + d], Y[o][k]);
                    }
                }
            }
        }

        // ---------- phase 4: softmax (unnormalized) + mix + store ----------
        float* op = out + ((size_t)bb * T + tb) * C + c0 + tx;
        #pragma unroll
        for (int p = 0; p < 4; ++p) {
            float lo[5], hi[5];
            #pragma unroll
            for (int k = 0; k < 5; ++k) upk2(lg[p][k], lo[k], hi[k]);
            {
                const int o = 2 * p;
                float e0 = ex2f(lo[0]), e1 = ex2f(lo[1]), e2 = ex2f(lo[2]),
                      e3 = ex2f(lo[3]), e4 = ex2f(lo[4]);
                float sum = ((e0 + e1) + (e2 + e3)) + e4;
                float dot = e0 * Y[o][0];
                dot = fmaf(e1, Y[o][1], dot);
                dot = fmaf(e2, Y[o][2], dot);
                dot = fmaf(e3, Y[o][3], dot);
                dot = fmaf(e4, Y[o][4], dot);
                op[(size_t)o * C] = dot * rcpf(sum);
            }
            {
                const int o = 2 * p + 1;
                float e0 = ex2f(hi[0]), e1 = ex2f(hi[1]), e2 = ex2f(hi[2]),
                      e3 = ex2f(hi[3]), e4 = ex2f(hi[4]);
                float sum = ((e0 + e1) + (e2 + e3)) + e4;
                float dot = e0 * Y[o][0];
                dot = fmaf(e1, Y[o][1], dot);
                dot = fmaf(e2, Y[o][2], dot);
                dot = fmaf(e3, Y[o][3], dot);
                dot = fmaf(e4, Y[o][4], dot);
                op[(size_t)o * C] = dot * rcpf(sum);
            }
        }
    }
}

// ---------------- launch ----------------
extern "C" void kernel_launch(void* const* d_in, const int* in_sizes, int n_in,
                              void* d_out, int out_size) {
    const float* x  = (const float*)d_in[0];
    const float* W1 = (const float*)d_in[1];
    const float* b1 = (const float*)d_in[2];
    const float* W2 = (const float*)d_in[3];
    const float* b2 = (const float*)d_in[4];
    float* out = (float*)d_out;

    const int B = 16, T = 4096, C = 256;
    size_t smem = (size_t)(WSF + 640) * sizeof(float);
    cudaFuncSetAttribute(agt_kernel, cudaFuncAttributeMaxDynamicSharedMemorySize, (int)smem);

    dim3 grid(C / CT, T / TT, B);
    dim3 block(CT, 2);
    agt_kernel<<<grid, block, smem>>>(x, W1, b1, W2, b2, out, B, T, C);
}

// round 9
// speedup vs baseline: 2.0482x; 1.0231x over previous
#include <cuda_runtime.h>
#include <math.h>

#define TT    128    // t-rows per block tile
#define CT    64     // channels per block tile
#define HALO  56     // max conv radius
#define ROWS  (TT + 2*HALO)   // 240
#define NTHREADS 256
#define RCHUNK 4     // outputs per thread per chunk
#define WSF   (ROWS * CT)     // float offset of duplicated weights in smem

typedef unsigned long long ull;

// ---------------- packed f32x2 helpers ----------------
__device__ __forceinline__ ull ffma2(ull a, ull b, ull c) {
    ull d; asm("fma.rn.f32x2 %0,%1,%2,%3;" : "=l"(d) : "l"(a), "l"(b), "l"(c)); return d;
}
__device__ __forceinline__ ull fmul2(ull a, ull b) {
    ull d; asm("mul.rn.f32x2 %0,%1,%2;" : "=l"(d) : "l"(a), "l"(b)); return d;
}
__device__ __forceinline__ ull pk2(float lo, float hi) {
    ull d; asm("mov.b64 %0,{%1,%2};" : "=l"(d) : "f"(lo), "f"(hi)); return d;
}
__device__ __forceinline__ void upk2(ull a, float& lo, float& hi) {
    asm("mov.b64 {%0,%1},%2;" : "=f"(lo), "=f"(hi) : "l"(a));
}
__device__ __forceinline__ float rcpf(float x) {
    float r; asm("rcp.approx.f32 %0,%1;" : "=f"(r) : "f"(x)); return r;
}
__device__ __forceinline__ float ex2f(float x) {
    float r; asm("ex2.approx.f32 %0,%1;" : "=f"(r) : "f"(x)); return r;
}
__device__ __forceinline__ float tanhf_a(float x) {
    float r; asm("tanh.approx.f32 %0,%1;" : "=f"(r) : "f"(x)); return r;
}

// ---------------- compile-time Gaussian bank ----------------
__host__ __device__ constexpr double cexp_(double x) {
    double y = x / 256.0;
    double s = 1.0, term = 1.0;
    for (int n = 1; n <= 24; ++n) { term = term * y / (double)n; s += term; }
    for (int i = 0; i < 8; ++i) s = s * s;
    return s;
}

struct BankT { float w[5][113]; };

__host__ __device__ constexpr BankT make_bank() {
    BankT b{};
    double sig[5] = {2.5, 4.0, 6.0, 9.0, 14.0};
    for (int k = 0; k < 5; ++k) {
        double s = sig[k];
        int r = (int)(4.0 * s);          // 10,16,24,36,56
        double sum = 0.0;
        for (int d = -r; d <= r; ++d) sum += cexp_(-0.5 * ((double)d / s) * ((double)d / s));
        for (int d = -r; d <= r; ++d)
            b.w[k][56 + d] = (float)(cexp_(-0.5 * ((double)d / s) * ((double)d / s)) / sum);
    }
    return b;
}

// ---------------- kernel ----------------
__global__ void __launch_bounds__(NTHREADS, 3)
agt_kernel(const float* __restrict__ x, const float* __restrict__ W1,
           const float* __restrict__ b1, const float* __restrict__ W2,
           const float* __restrict__ b2, float* __restrict__ out,
           int B, int T, int C)
{
    constexpr BankT BANK = make_bank();
    constexpr int RAD[5] = {10, 16, 24, 36, 56};

    extern __shared__ float sm[];
    float* S   = sm;               // ROWS * CT tile
    float* ws2 = sm + WSF;         // duplicated weights: 586 floats

    const int tx  = threadIdx.x;           // channel in tile (0..63)
    const int ty  = threadIdx.y;           // quarter of the t-tile (0..3)
    const int tid = ty * CT + tx;
    const int c0  = blockIdx.x * CT;
    const int t0  = blockIdx.y * TT;
    const int bb  = blockIdx.z;

    // --- stage duplicated weights: [W1(96)|b1(32)|W2'(160)|b2'(5)] ---
    // tanh-GELU: gelu = 0.5*z*(1+tanh(u)); fold 0.5*log2(e) into W2', log2(e)
    // into b2' so lg accumulates log2e*logits (softmax uses ex2 directly) and
    // the MLP computes g' = z + z*tanh(u) = 2*gelu.
    for (int i = tid; i < 293; i += NTHREADS) {
        float v;
        if      (i <  96) v = W1[i];
        else if (i < 128) v = b1[i - 96];
        else if (i < 288) v = W2[i - 128] * (0.5f * 1.4426950408889634f);
        else              v = b2[i - 288] * 1.4426950408889634f;
        ws2[2 * i]     = v;
        ws2[2 * i + 1] = v;
    }

    // --- stage x tile (zero padded outside [0,T) for the conv) ---
    const float* xb = x + ((size_t)bb * T) * C + c0;
    for (int idx = tid; idx < ROWS * CT; idx += NTHREADS) {
        int r  = idx >> 6;          // / CT
        int cc = idx & (CT - 1);
        int g  = t0 - HALO + r;
        float v = 0.0f;
        if (g >= 0 && g < T) v = xb[(size_t)g * C + cc];
        S[idx] = v;
    }
    __syncthreads();

    const float* Scol = S + tx;
    const ull*   wp   = (const ull*)ws2;   // pair index == flat weight index

    // tanh-GELU: u = z*(CT1 + CT2*z^2), CT1=sqrt(2/pi), CT2=sqrt(2/pi)*0.044715
    const ull CT1 = pk2(0.7978845608f, 0.7978845608f);
    const ull CT2 = pk2(0.0356774081f, 0.0356774081f);

    const bool interior = (t0 >= 8) && (t0 + TT + 8 <= T);

    #pragma unroll 1
    for (int chunk = 0; chunk < TT / (4 * RCHUNK); ++chunk) {   // 8 iterations
        const int lb = ty * (TT / 4) + chunk * RCHUNK;  // local first output row
        const int tb = t0 + lb;                         // global first output row
        const float* Sp = Scol + lb * CT;               // Sp[r*CT] = S[(lb+r)*CT+tx]

        // ---------- phase 1: mean / var over 16-window, plus x ----------
        float m[RCHUNK], va[RCHUNK], xv[RCHUNK];
        if (interior) {
            float s = 0.0f, s2 = 0.0f;
            #pragma unroll
            for (int u = -7; u <= 8; ++u) {
                float w = Sp[(HALO + u) * CT];
                s += w; s2 += w * w;
            }
            #pragma unroll
            for (int i = 0; i < RCHUNK; ++i) {
                if (i > 0) {
                    float wa = Sp[(HALO + i + 8) * CT];
                    float wr = Sp[(HALO + i - 8) * CT];
                    s  += wa - wr;
                    s2 += wa * wa - wr * wr;
                }
                float mm  = s  * (1.0f / 16.0f);
                float m2v = s2 * (1.0f / 16.0f);
                m[i]  = mm;
                va[i] = fmaxf(m2v - mm * mm, 0.0f);
                xv[i] = Sp[(HALO + i) * CT];
            }
        } else {
            float s = 0.0f, s2 = 0.0f;
            #pragma unroll
            for (int u = -7; u <= 8; ++u) {
                int g = tb + u;
                g = (g < 0)  ? -g              : g;
                g = (g >= T) ? (2 * T - 2 - g) : g;
                float w = Scol[(g - t0 + HALO) * CT];
                s += w; s2 += w * w;
            }
            #pragma unroll
            for (int i = 0; i < RCHUNK; ++i) {
                if (i > 0) {
                    int ga = tb + i + 8;  ga = (ga >= T) ? (2 * T - 2 - ga) : ga;
                    int gr = tb + i - 8;  gr = (gr < 0)  ? -gr              : gr;
                    float wa = Scol[(ga - t0 + HALO) * CT];
                    float wr = Scol[(gr - t0 + HALO) * CT];
                    s  += wa - wr;
                    s2 += wa * wa - wr * wr;
                }
                float mm  = s  * (1.0f / 16.0f);
                float m2v = s2 * (1.0f / 16.0f);
                m[i]  = mm;
                va[i] = fmaxf(m2v - mm * mm, 0.0f);
                xv[i] = Sp[(HALO + i) * CT];
            }
        }

        // pack features into f32x2 pairs (i, i+1)
        ull m2[2], v2p[2], x2[2];
        #pragma unroll
        for (int p = 0; p < 2; ++p) {
            m2[p]  = pk2(m[2 * p],  m[2 * p + 1]);
            v2p[p] = pk2(va[2 * p], va[2 * p + 1]);
            x2[p]  = pk2(xv[2 * p], xv[2 * p + 1]);
        }

        // ---------- phase 2: conditioner MLP, packed tanh.approx GELU ----------
        ull lg[2][5];
        #pragma unroll
        for (int p = 0; p < 2; ++p)
            #pragma unroll
            for (int k = 0; k < 5; ++k) lg[p][k] = wp[288 + k];   // b2' pair

        #pragma unroll 2
        for (int j = 0; j < 32; ++j) {
            ull w1m = wp[j], w1v = wp[32 + j], w1x = wp[64 + j], bj = wp[96 + j];
            ull w20 = wp[128 + 5 * j + 0];
            ull w21 = wp[128 + 5 * j + 1];
            ull w22 = wp[128 + 5 * j + 2];
            ull w23 = wp[128 + 5 * j + 3];
            ull w24 = wp[128 + 5 * j + 4];
            #pragma unroll
            for (int p = 0; p < 2; ++p) {
                ull z  = ffma2(m2[p], w1m, ffma2(v2p[p], w1v, ffma2(x2[p], w1x, bj)));
                ull zz = fmul2(z, z);
                ull u  = fmul2(z, ffma2(zz, CT2, CT1));
                float ul, uh; upk2(u, ul, uh);
                ull th = pk2(tanhf_a(ul), tanhf_a(uh));
                ull g  = ffma2(z, th, z);        // g' = z*(1 + tanh(u)) = 2*gelu
                lg[p][0] = ffma2(g, w20, lg[p][0]);
                lg[p][1] = ffma2(g, w21, lg[p][1]);
                lg[p][2] = ffma2(g, w22, lg[p][2]);
                lg[p][3] = ffma2(g, w23, lg[p][3]);
                lg[p][4] = ffma2(g, w24, lg[p][4]);
            }
        }

        // convert logits -> unnormalized softmax weights now (frees lg chains)
        float wgt[RCHUNK][5];
        #pragma unroll
        for (int p = 0; p < 2; ++p) {
            float lo[5], hi[5];
            #pragma unroll
            for (int k = 0; k < 5; ++k) upk2(lg[p][k], lo[k], hi[k]);
            #pragma unroll
            for (int k = 0; k < 5; ++k) { wgt[2*p][k] = ex2f(lo[k]); wgt[2*p+1][k] = ex2f(hi[k]); }
        }

        // ---------- phase 3: symmetric 5-sigma conv (ring-buffer windows) ----------
        float Y[RCHUNK][5];
        float Lb[RCHUNK], Rb[RCHUNK];
        #pragma unroll
        for (int o = 0; o < RCHUNK; ++o) {
            float vc = Sp[(HALO + o) * CT];   // slot (56+o)&3 == o
            Lb[o] = vc; Rb[o] = vc;
            #pragma unroll
            for (int k = 0; k < 5; ++k) Y[o][k] = vc * BANK.w[k][56];
        }
        #pragma unroll
        for (int d = 1; d <= 56; ++d) {
            Lb[(64 - d) & 3] = Sp[(HALO - d) * CT];
            Rb[(RCHUNK - 1 + d) & 3] = Sp[(HALO + RCHUNK - 1 + d) * CT];
            #pragma unroll
            for (int o = 0; o < RCHUNK; ++o) {
                float Lv = Lb[(64 + o - d) & 3];
                float Rv = Rb[(o + d) & 3];
                if (d > RAD[1]) {
                    // only sigma tails active: two FFMA-imm beat FADD+FFMA
                    #pragma unroll
                    for (int k = 0; k < 5; ++k) {
                        if (d <= RAD[k]) {
                            Y[o][k] = fmaf(Lv, BANK.w[k][56 + d], Y[o][k]);
                            Y[o][k] = fmaf(Rv, BANK.w[k][56 + d], Y[o][k]);
                        }
                    }
                } else {
                    float s = Lv + Rv;
                    #pragma unroll
                    for (int k = 0; k < 5; ++k) {
                        if (d <= RAD[k])
                            Y[o][k] = fmaf(s, BANK.w[k][56 + d], Y[o][k]);
                    }
                }
            }
        }

        // ---------- phase 4: mix + store ----------
        float* op = out + ((size_t)bb * T + tb) * C + c0 + tx;
        #pragma unroll
        for (int o = 0; o < RCHUNK; ++o) {
            float sum = ((wgt[o][0] + wgt[o][1]) + (wgt[o][2] + wgt[o][3])) + wgt[o][4];
            float dot = wgt[o][0] * Y[o][0];
            dot = fmaf(wgt[o][1], Y[o][1], dot);
            dot = fmaf(wgt[o][2], Y[o][2], dot);
            dot = fmaf(wgt[o][3], Y[o][3], dot);
            dot = fmaf(wgt[o][4], Y[o][4], dot);
            op[(size_t)o * C] = dot * rcpf(sum);
        }
    }
}

// ---------------- launch ----------------
extern "C" void kernel_launch(void* const* d_in, const int* in_sizes, int n_in,
                              void* d_out, int out_size) {
    const float* x  = (const float*)d_in[0];
    const float* W1 = (const float*)d_in[1];
    const float* b1 = (const float*)d_in[2];
    const float* W2 = (const float*)d_in[3];
    const float* b2 = (const float*)d_in[4];
    float* out = (float*)d_out;

    const int B = 16, T = 4096, C = 256;
    size_t smem = (size_t)(WSF + 640) * sizeof(float);
    cudaFuncSetAttribute(agt_kernel, cudaFuncAttributeMaxDynamicSharedMemorySize, (int)smem);

    dim3 grid(C / CT, T / TT, B);
    dim3 block(CT, 4);
    agt_kernel<<<grid, block, smem>>>(x, W1, b1, W2, b2, out, B, T, C);
}

// round 10
// speedup vs baseline: 2.1897x; 1.0691x over previous
#include <cuda_runtime.h>
#include <math.h>

#define TT    256    // t-rows per block tile
#define CT    32     // channels per block tile
#define HALO  56     // max conv radius
#define ROWS  (TT + 2*HALO)   // 368
#define NTHREADS 256
#define NTY   8      // t-groups per block
#define RCHUNK 4     // outputs per thread per chunk
#define WSF   (ROWS * CT)     // float offset of duplicated weights in smem

typedef unsigned long long ull;

// ---------------- packed f32x2 helpers ----------------
__device__ __forceinline__ ull ffma2(ull a, ull b, ull c) {
    ull d; asm("fma.rn.f32x2 %0,%1,%2,%3;" : "=l"(d) : "l"(a), "l"(b), "l"(c)); return d;
}
__device__ __forceinline__ ull fmul2(ull a, ull b) {
    ull d; asm("mul.rn.f32x2 %0,%1,%2;" : "=l"(d) : "l"(a), "l"(b)); return d;
}
__device__ __forceinline__ ull pk2(float lo, float hi) {
    ull d; asm("mov.b64 %0,{%1,%2};" : "=l"(d) : "f"(lo), "f"(hi)); return d;
}
__device__ __forceinline__ void upk2(ull a, float& lo, float& hi) {
    asm("mov.b64 {%0,%1},%2;" : "=f"(lo), "=f"(hi) : "l"(a));
}
__device__ __forceinline__ float rcpf(float x) {
    float r; asm("rcp.approx.f32 %0,%1;" : "=f"(r) : "f"(x)); return r;
}
__device__ __forceinline__ float ex2f(float x) {
    float r; asm("ex2.approx.f32 %0,%1;" : "=f"(r) : "f"(x)); return r;
}
__device__ __forceinline__ float tanhf_a(float x) {
    float r; asm("tanh.approx.f32 %0,%1;" : "=f"(r) : "f"(x)); return r;
}

// ---------------- compile-time Gaussian bank ----------------
__host__ __device__ constexpr double cexp_(double x) {
    double y = x / 256.0;
    double s = 1.0, term = 1.0;
    for (int n = 1; n <= 24; ++n) { term = term * y / (double)n; s += term; }
    for (int i = 0; i < 8; ++i) s = s * s;
    return s;
}

struct BankT { float w[5][113]; };

__host__ __device__ constexpr BankT make_bank() {
    BankT b{};
    double sig[5] = {2.5, 4.0, 6.0, 9.0, 14.0};
    for (int k = 0; k < 5; ++k) {
        double s = sig[k];
        int r = (int)(4.0 * s);          // 10,16,24,36,56
        double sum = 0.0;
        for (int d = -r; d <= r; ++d) sum += cexp_(-0.5 * ((double)d / s) * ((double)d / s));
        for (int d = -r; d <= r; ++d)
            b.w[k][56 + d] = (float)(cexp_(-0.5 * ((double)d / s) * ((double)d / s)) / sum);
    }
    return b;
}

// ---------------- kernel ----------------
__global__ void __launch_bounds__(NTHREADS, 4)
agt_kernel(const float* __restrict__ x, const float* __restrict__ W1,
           const float* __restrict__ b1, const float* __restrict__ W2,
           const float* __restrict__ b2, float* __restrict__ out,
           int B, int T, int C)
{
    constexpr BankT BANK = make_bank();
    constexpr int RAD[5] = {10, 16, 24, 36, 56};

    extern __shared__ float sm[];
    float* S   = sm;               // ROWS * CT tile
    float* ws2 = sm + WSF;         // duplicated weights: 520 floats

    const int tx  = threadIdx.x;           // channel in tile (0..31) = lane
    const int ty  = threadIdx.y;           // t-group (0..7) = warp id
    const int tid = ty * CT + tx;
    const int c0  = blockIdx.x * CT;
    const int t0  = blockIdx.y * TT;
    const int bb  = blockIdx.z;

    // --- stage duplicated weights: [W1(96)|b1(32)|W2d(128)|b2d(4)] ---
    // tanh-GELU with 0.5*log2(e) folded into the W2 *difference* weights
    // (softmax shift-invariance: accumulate lg_k - lg_4, e4 == 1):
    //   W2d[j][k] = (W2[j][k]-W2[j][4]) * 0.5*log2(e),  b2d[k] = (b2[k]-b2[4])*log2(e)
    for (int i = tid; i < 260; i += NTHREADS) {
        float v;
        if      (i <  96) v = W1[i];
        else if (i < 128) v = b1[i - 96];
        else if (i < 256) {
            int j = (i - 128) >> 2, k = (i - 128) & 3;
            v = (W2[j * 5 + k] - W2[j * 5 + 4]) * (0.5f * 1.4426950408889634f);
        } else {
            int k = i - 256;
            v = (b2[k] - b2[4]) * 1.4426950408889634f;
        }
        ws2[2 * i]     = v;
        ws2[2 * i + 1] = v;
    }

    // --- stage x tile (zero padded outside [0,T) for the conv) ---
    const float* xb = x + ((size_t)bb * T) * C + c0;
    for (int idx = tid; idx < ROWS * CT; idx += NTHREADS) {
        int r  = idx >> 5;          // / CT
        int cc = idx & (CT - 1);
        int g  = t0 - HALO + r;
        float v = 0.0f;
        if (g >= 0 && g < T) v = xb[(size_t)g * C + cc];
        S[idx] = v;
    }
    __syncthreads();

    const float* Scol = S + tx;
    const ull*   wp   = (const ull*)ws2;   // pair index == flat weight index

    // tanh-GELU: u = z*(CT1 + CT2*z^2), CT1=sqrt(2/pi), CT2=sqrt(2/pi)*0.044715
    const ull CK1 = pk2(0.7978845608f, 0.7978845608f);
    const ull CK2 = pk2(0.0356774081f, 0.0356774081f);

    const bool interior = (t0 >= 8) && (t0 + TT + 8 <= T);

    #pragma unroll 1
    for (int chunk = 0; chunk < TT / (NTY * RCHUNK); ++chunk) {   // 8 iterations
        const int lb = ty * (TT / NTY) + chunk * RCHUNK;  // local first output row
        const int tb = t0 + lb;                           // global first output row
        const float* Sp = Scol + lb * CT;                 // Sp[r*CT] = S[(lb+r)*CT+tx]

        // ---------- phase 1: mean / var over 16-window, plus x ----------
        float m[RCHUNK], va[RCHUNK], xv[RCHUNK];
        if (interior) {
            float s = 0.0f, s2 = 0.0f;
            #pragma unroll
            for (int u = -7; u <= 8; ++u) {
                float w = Sp[(HALO + u) * CT];
                s += w; s2 += w * w;
            }
            #pragma unroll
            for (int i = 0; i < RCHUNK; ++i) {
                if (i > 0) {
                    float wa = Sp[(HALO + i + 8) * CT];
                    float wr = Sp[(HALO + i - 8) * CT];
                    s  += wa - wr;
                    s2 += wa * wa - wr * wr;
                }
                float mm  = s  * (1.0f / 16.0f);
                float m2v = s2 * (1.0f / 16.0f);
                m[i]  = mm;
                va[i] = fmaxf(m2v - mm * mm, 0.0f);
                xv[i] = Sp[(HALO + i) * CT];
            }
        } else {
            float s = 0.0f, s2 = 0.0f;
            #pragma unroll
            for (int u = -7; u <= 8; ++u) {
                int g = tb + u;
                g = (g < 0)  ? -g              : g;
                g = (g >= T) ? (2 * T - 2 - g) : g;
                float w = Scol[(g - t0 + HALO) * CT];
                s += w; s2 += w * w;
            }
            #pragma unroll
            for (int i = 0; i < RCHUNK; ++i) {
                if (i > 0) {
                    int ga = tb + i + 8;  ga = (ga >= T) ? (2 * T - 2 - ga) : ga;
                    int gr = tb + i - 8;  gr = (gr < 0)  ? -gr              : gr;
                    float wa = Scol[(ga - t0 + HALO) * CT];
                    float wr = Scol[(gr - t0 + HALO) * CT];
                    s  += wa - wr;
                    s2 += wa * wa - wr * wr;
                }
                float mm  = s  * (1.0f / 16.0f);
                float m2v = s2 * (1.0f / 16.0f);
                m[i]  = mm;
                va[i] = fmaxf(m2v - mm * mm, 0.0f);
                xv[i] = Sp[(HALO + i) * CT];
            }
        }

        // pack features into f32x2 pairs (i, i+1)
        ull m2[2], v2p[2], x2[2];
        #pragma unroll
        for (int p = 0; p < 2; ++p) {
            m2[p]  = pk2(m[2 * p],  m[2 * p + 1]);
            v2p[p] = pk2(va[2 * p], va[2 * p + 1]);
            x2[p]  = pk2(xv[2 * p], xv[2 * p + 1]);
        }

        // ---------- phase 2: conditioner MLP, packed tanh.approx GELU ----------
        // lg[p][k] accumulates log2e*(logit_k - logit_4) for output pair p
        ull lg[2][4];
        #pragma unroll
        for (int p = 0; p < 2; ++p)
            #pragma unroll
            for (int k = 0; k < 4; ++k) lg[p][k] = wp[256 + k];   // b2d pair

        #pragma unroll 2
        for (int j = 0; j < 32; ++j) {
            ull w1m = wp[j], w1v = wp[32 + j], w1x = wp[64 + j], bj = wp[96 + j];
            ull w20 = wp[128 + 4 * j + 0];
            ull w21 = wp[128 + 4 * j + 1];
            ull w22 = wp[128 + 4 * j + 2];
            ull w23 = wp[128 + 4 * j + 3];
            #pragma unroll
            for (int p = 0; p < 2; ++p) {
                ull z  = ffma2(m2[p], w1m, ffma2(v2p[p], w1v, ffma2(x2[p], w1x, bj)));
                ull zz = fmul2(z, z);
                ull u  = fmul2(z, ffma2(zz, CK2, CK1));
                float ul, uh; upk2(u, ul, uh);
                ull th = pk2(tanhf_a(ul), tanhf_a(uh));
                ull g  = ffma2(z, th, z);        // g' = z*(1 + tanh(u)) = 2*gelu
                lg[p][0] = ffma2(g, w20, lg[p][0]);
                lg[p][1] = ffma2(g, w21, lg[p][1]);
                lg[p][2] = ffma2(g, w22, lg[p][2]);
                lg[p][3] = ffma2(g, w23, lg[p][3]);
            }
        }

        // ---------- phase 3: symmetric 5-sigma conv (ring-buffer windows) ----------
        float Y[RCHUNK][5];
        float Lb[RCHUNK], Rb[RCHUNK];
        #pragma unroll
        for (int o = 0; o < RCHUNK; ++o) {
            float vc = Sp[(HALO + o) * CT];
            Lb[o] = vc; Rb[o] = vc;
            #pragma unroll
            for (int k = 0; k < 5; ++k) Y[o][k] = vc * BANK.w[k][56];
        }
        #pragma unroll
        for (int d = 1; d <= 56; ++d) {
            Lb[(64 - d) & 3] = Sp[(HALO - d) * CT];
            Rb[(RCHUNK - 1 + d) & 3] = Sp[(HALO + RCHUNK - 1 + d) * CT];
            #pragma unroll
            for (int o = 0; o < RCHUNK; ++o) {
                float Lv = Lb[(64 + o - d) & 3];
                float Rv = Rb[(o + d) & 3];
                if (d > RAD[1]) {
                    // only sigma tails active: two FFMA-imm beat FADD+FFMA
                    #pragma unroll
                    for (int k = 0; k < 5; ++k) {
                        if (d <= RAD[k]) {
                            Y[o][k] = fmaf(Lv, BANK.w[k][56 + d], Y[o][k]);
                            Y[o][k] = fmaf(Rv, BANK.w[k][56 + d], Y[o][k]);
                        }
                    }
                } else {
                    float s = Lv + Rv;
                    #pragma unroll
                    for (int k = 0; k < 5; ++k) {
                        if (d <= RAD[k])
                            Y[o][k] = fmaf(s, BANK.w[k][56 + d], Y[o][k]);
                    }
                }
            }
        }

        // ---------- phase 4: softmax (e4 = 1) + mix + store ----------
        float* op = out + ((size_t)bb * T + tb) * C + c0 + tx;
        #pragma unroll
        for (int p = 0; p < 2; ++p) {
            float lo[4], hi[4];
            #pragma unroll
            for (int k = 0; k < 4; ++k) upk2(lg[p][k], lo[k], hi[k]);
            {
                const int o = 2 * p;
                float e0 = ex2f(lo[0]), e1 = ex2f(lo[1]), e2 = ex2f(lo[2]), e3 = ex2f(lo[3]);
                float sum = ((e0 + e1) + (e2 + e3)) + 1.0f;
                float dot = fmaf(e0, Y[o][0], Y[o][4]);
                dot = fmaf(e1, Y[o][1], dot);
                dot = fmaf(e2, Y[o][2], dot);
                dot = fmaf(e3, Y[o][3], dot);
                op[(size_t)o * C] = dot * rcpf(sum);
            }
            {
                const int o = 2 * p + 1;
                float e0 = ex2f(hi[0]), e1 = ex2f(hi[1]), e2 = ex2f(hi[2]), e3 = ex2f(hi[3]);
                float sum = ((e0 + e1) + (e2 + e3)) + 1.0f;
                float dot = fmaf(e0, Y[o][0], Y[o][4]);
                dot = fmaf(e1, Y[o][1], dot);
                dot = fmaf(e2, Y[o][2], dot);
                dot = fmaf(e3, Y[o][3], dot);
                op[(size_t)o * C] = dot * rcpf(sum);
            }
        }
    }
}

// ---------------- launch ----------------
extern "C" void kernel_launch(void* const* d_in, const int* in_sizes, int n_in,
                              void* d_out, int out_size) {
    const float* x  = (const float*)d_in[0];
    const float* W1 = (const float*)d_in[1];
    const float* b1 = (const float*)d_in[2];
    const float* W2 = (const float*)d_in[3];
    const float* b2 = (const float*)d_in[4];
    float* out = (float*)d_out;

    const int B = 16, T = 4096, C = 256;
    size_t smem = (size_t)(WSF + 576) * sizeof(float);
    cudaFuncSetAttribute(agt_kernel, cudaFuncAttributeMaxDynamicSharedMemorySize, (int)smem);

    dim3 grid(C / CT, T / TT, B);
    dim3 block(CT, NTY);
    agt_kernel<<<grid, block, smem>>>(x, W1, b1, W2, b2, out, B, T, C);
}

// round 11
// speedup vs baseline: 2.2347x; 1.0205x over previous
#include <cuda_runtime.h>
#include <math.h>

#define TT    256    // t-rows per block tile
#define CT    32     // channels per block tile
#define HALO  56     // max conv radius
#define ROWS  (TT + 2*HALO)   // 368
#define ROWSP 372    // padded column stride (mult of 4 for LDS.128 alignment)
#define NTHREADS 256
#define NTY   8      // t-groups per block
#define RCHUNK 4     // outputs per thread per chunk
#define WSF   (CT * ROWSP)    // float offset of duplicated weights in smem

typedef unsigned long long ull;

// ---------------- packed f32x2 helpers ----------------
__device__ __forceinline__ ull ffma2(ull a, ull b, ull c) {
    ull d; asm("fma.rn.f32x2 %0,%1,%2,%3;" : "=l"(d) : "l"(a), "l"(b), "l"(c)); return d;
}
__device__ __forceinline__ ull fmul2(ull a, ull b) {
    ull d; asm("mul.rn.f32x2 %0,%1,%2;" : "=l"(d) : "l"(a), "l"(b)); return d;
}
__device__ __forceinline__ ull pk2(float lo, float hi) {
    ull d; asm("mov.b64 %0,{%1,%2};" : "=l"(d) : "f"(lo), "f"(hi)); return d;
}
__device__ __forceinline__ void upk2(ull a, float& lo, float& hi) {
    asm("mov.b64 {%0,%1},%2;" : "=f"(lo), "=f"(hi) : "l"(a));
}
__device__ __forceinline__ float rcpf(float x) {
    float r; asm("rcp.approx.f32 %0,%1;" : "=f"(r) : "f"(x)); return r;
}
__device__ __forceinline__ float ex2f(float x) {
    float r; asm("ex2.approx.f32 %0,%1;" : "=f"(r) : "f"(x)); return r;
}
__device__ __forceinline__ float tanhf_a(float x) {
    float r; asm("tanh.approx.f32 %0,%1;" : "=f"(r) : "f"(x)); return r;
}

// ---------------- compile-time Gaussian bank ----------------
__host__ __device__ constexpr double cexp_(double x) {
    double y = x / 256.0;
    double s = 1.0, term = 1.0;
    for (int n = 1; n <= 24; ++n) { term = term * y / (double)n; s += term; }
    for (int i = 0; i < 8; ++i) s = s * s;
    return s;
}

struct BankT { float w[5][113]; };

__host__ __device__ constexpr BankT make_bank() {
    BankT b{};
    double sig[5] = {2.5, 4.0, 6.0, 9.0, 14.0};
    for (int k = 0; k < 5; ++k) {
        double s = sig[k];
        int r = (int)(4.0 * s);          // 10,16,24,36,56
        double sum = 0.0;
        for (int d = -r; d <= r; ++d) sum += cexp_(-0.5 * ((double)d / s) * ((double)d / s));
        for (int d = -r; d <= r; ++d)
            b.w[k][56 + d] = (float)(cexp_(-0.5 * ((double)d / s) * ((double)d / s)) / sum);
    }
    return b;
}

// ---------------- kernel ----------------
__global__ void __launch_bounds__(NTHREADS, 4)
agt_kernel(const float* __restrict__ x, const float* __restrict__ W1,
           const float* __restrict__ b1, const float* __restrict__ W2,
           const float* __restrict__ b2, float* __restrict__ out,
           int B, int T, int C)
{
    constexpr BankT BANK = make_bank();
    constexpr int RAD[5] = {10, 16, 24, 36, 56};

    extern __shared__ float sm[];
    float* S   = sm;               // transposed tile: S[cc*ROWSP + r]
    float* ws2 = sm + WSF;         // duplicated weights: 520 floats

    const int tx  = threadIdx.x;           // channel in tile (0..31) = lane
    const int ty  = threadIdx.y;           // t-group (0..7) = warp id
    const int tid = ty * CT + tx;
    const int c0  = blockIdx.x * CT;
    const int t0  = blockIdx.y * TT;
    const int bb  = blockIdx.z;

    // --- stage duplicated weights: [W1(96)|b1(32)|W2d(128)|b2d(4)] ---
    // 4-logit softmax: W2d[j][k] = (W2[j][k]-W2[j][4]) * 0.5*log2(e),
    //                  b2d[k]    = (b2[k]-b2[4]) * log2(e);   e4 == 1.
    for (int i = tid; i < 260; i += NTHREADS) {
        float v;
        if      (i <  96) v = W1[i];
        else if (i < 128) v = b1[i - 96];
        else if (i < 256) {
            int j = (i - 128) >> 2, k = (i - 128) & 3;
            v = (W2[j * 5 + k] - W2[j * 5 + 4]) * (0.5f * 1.4426950408889634f);
        } else {
            int k = i - 256;
            v = (b2[k] - b2[4]) * 1.4426950408889634f;
        }
        ws2[2 * i]     = v;
        ws2[2 * i + 1] = v;
    }

    // --- stage x tile TRANSPOSED (zero padded outside [0,T)) ---
    const float* xb = x + ((size_t)bb * T) * C + c0;
    for (int idx = tid; idx < ROWS * CT; idx += NTHREADS) {
        int r  = idx >> 5;          // row
        int cc = idx & (CT - 1);    // channel (lane) -> coalesced gmem read
        int g  = t0 - HALO + r;
        float v = 0.0f;
        if (g >= 0 && g < T) v = xb[(size_t)g * C + cc];
        S[cc * ROWSP + r] = v;
    }
    __syncthreads();

    const float* colp = S + tx * ROWSP;    // this thread's channel column
    const ull*   wp   = (const ull*)ws2;   // pair index == flat weight index

    // tanh-GELU: u = z*(CK1 + CK2*z^2)
    const ull CK1 = pk2(0.7978845608f, 0.7978845608f);
    const ull CK2 = pk2(0.0356774081f, 0.0356774081f);

    const bool interior = (t0 >= 8) && (t0 + TT + 8 <= T);
    const int  lb0 = ty * (TT / NTY);      // first local output row of this warp
    const int  tb0 = t0 + lb0;

    // ---- carried sliding sums: init window of virtual output (tb0-1):
    // rows tb0-8 .. tb0+7  (local: lb0+HALO-8 .. lb0+HALO+7)
    float s = 0.0f, s2 = 0.0f;
    if (interior) {
        #pragma unroll
        for (int u = -8; u <= 7; ++u) {
            float w = colp[lb0 + HALO + u];
            s += w; s2 += w * w;
        }
    } else {
        #pragma unroll
        for (int u = -8; u <= 7; ++u) {
            int g = tb0 + u;
            g = (g < 0)  ? -g              : g;
            g = (g >= T) ? (2 * T - 2 - g) : g;
            float w = colp[g - t0 + HALO];
            s += w; s2 += w * w;
        }
    }

    #pragma unroll 1
    for (int chunk = 0; chunk < TT / (NTY * RCHUNK); ++chunk) {   // 8 iterations
        const int lb = lb0 + chunk * RCHUNK;   // local first output row
        const int tb = t0 + lb;                // global first output row
        const int b0 = lb + HALO;              // tile row of output 0 (b0 % 4 == 0)

        // center taps (also xv): rows b0..b0+3, 16B aligned
        const float4 cq = *(const float4*)&colp[b0];
        const float cqa[4] = {cq.x, cq.y, cq.z, cq.w};

        // ---------- phase 1: carried mean / var (uniform update per output) ----------
        float m[RCHUNK], va[RCHUNK];
        if (interior) {
            #pragma unroll
            for (int i = 0; i < RCHUNK; ++i) {
                float wa = colp[b0 + i + 8];
                float wr = colp[b0 + i - 8];
                s  += wa - wr;
                s2 += wa * wa - wr * wr;
                float mm  = s  * (1.0f / 16.0f);
                float m2v = s2 * (1.0f / 16.0f);
                m[i]  = mm;
                va[i] = fmaxf(m2v - mm * mm, 0.0f);
            }
        } else {
            #pragma unroll
            for (int i = 0; i < RCHUNK; ++i) {
                int ga = tb + i + 8;  ga = (ga >= T) ? (2 * T - 2 - ga) : ga;
                int gr = tb + i - 8;  gr = (gr < 0)  ? -gr              : gr;
                float wa = colp[ga - t0 + HALO];
                float wr = colp[gr - t0 + HALO];
                s  += wa - wr;
                s2 += wa * wa - wr * wr;
                float mm  = s  * (1.0f / 16.0f);
                float m2v = s2 * (1.0f / 16.0f);
                m[i]  = mm;
                va[i] = fmaxf(m2v - mm * mm, 0.0f);
            }
        }

        // pack features into f32x2 pairs (i, i+1)
        ull m2[2], v2p[2], x2[2];
        #pragma unroll
        for (int p = 0; p < 2; ++p) {
            m2[p]  = pk2(m[2 * p],  m[2 * p + 1]);
            v2p[p] = pk2(va[2 * p], va[2 * p + 1]);
            x2[p]  = pk2(cqa[2 * p], cqa[2 * p + 1]);
        }

        // ---------- phase 2: conditioner MLP, packed tanh.approx GELU ----------
        ull lg[2][4];
        #pragma unroll
        for (int p = 0; p < 2; ++p)
            #pragma unroll
            for (int k = 0; k < 4; ++k) lg[p][k] = wp[256 + k];   // b2d pair

        #pragma unroll 2
        for (int j = 0; j < 32; ++j) {
            ull w1m = wp[j], w1v = wp[32 + j], w1x = wp[64 + j], bj = wp[96 + j];
            ull w20 = wp[128 + 4 * j + 0];
            ull w21 = wp[128 + 4 * j + 1];
            ull w22 = wp[128 + 4 * j + 2];
            ull w23 = wp[128 + 4 * j + 3];
            #pragma unroll
            for (int p = 0; p < 2; ++p) {
                ull z  = ffma2(m2[p], w1m, ffma2(v2p[p], w1v, ffma2(x2[p], w1x, bj)));
                ull zz = fmul2(z, z);
                ull u  = fmul2(z, ffma2(zz, CK2, CK1));
                float ul, uh; upk2(u, ul, uh);
                ull th = pk2(tanhf_a(ul), tanhf_a(uh));
                ull g  = ffma2(z, th, z);        // g' = z*(1 + tanh(u)) = 2*gelu
                lg[p][0] = ffma2(g, w20, lg[p][0]);
                lg[p][1] = ffma2(g, w21, lg[p][1]);
                lg[p][2] = ffma2(g, w22, lg[p][2]);
                lg[p][3] = ffma2(g, w23, lg[p][3]);
            }
        }

        // logits -> unnormalized softmax weights (e4 == 1), frees lg
        float ew[RCHUNK][4];
        #pragma unroll
        for (int p = 0; p < 2; ++p) {
            float lo, hi;
            #pragma unroll
            for (int k = 0; k < 4; ++k) {
                upk2(lg[p][k], lo, hi);
                ew[2 * p][k]     = ex2f(lo);
                ew[2 * p + 1][k] = ex2f(hi);
            }
        }

        // ---------- phase 3: symmetric conv, float4-streamed columns ----------
        float Y[RCHUNK][5];
        #pragma unroll
        for (int o = 0; o < RCHUNK; ++o)
            #pragma unroll
            for (int k = 0; k < 5; ++k) Y[o][k] = cqa[o] * BANK.w[k][56];

        float Lp[4] = {cqa[0], cqa[1], cqa[2], cqa[3]};  // rows b0..b0+3
        float Rp[4] = {cqa[0], cqa[1], cqa[2], cqa[3]};  // rows b0..b0+3
        #pragma unroll
        for (int g14 = 0; g14 < 14; ++g14) {
            const float4 lq = *(const float4*)&colp[b0 - 4 * g14 - 4]; // rows b0-4g-4+e
            const float4 rq = *(const float4*)&colp[b0 + 4 * g14 + 4]; // rows b0+4g+4+e
            const float Lc[4] = {lq.x, lq.y, lq.z, lq.w};
            const float Rc[4] = {rq.x, rq.y, rq.z, rq.w};
            #pragma unroll
            for (int dd = 1; dd <= 4; ++dd) {
                const int d = 4 * g14 + dd;
                #pragma unroll
                for (int o = 0; o < RCHUNK; ++o) {
                    const int el = 4 - dd + o;          // L row b0-d+o
                    const int er = dd + o;              // R row b0+d+o
                    float Lv = (el < 4) ? Lc[el] : Lp[el - 4];
                    float Rv = (er < 4) ? Rp[er] : Rc[er - 4];
                    if (d > RAD[1]) {
                        #pragma unroll
                        for (int k = 0; k < 5; ++k) {
                            if (d <= RAD[k]) {
                                Y[o][k] = fmaf(Lv, BANK.w[k][56 + d], Y[o][k]);
                                Y[o][k] = fmaf(Rv, BANK.w[k][56 + d], Y[o][k]);
                            }
                        }
                    } else {
                        float sv = Lv + Rv;
                        #pragma unroll
                        for (int k = 0; k < 5; ++k) {
                            if (d <= RAD[k])
                                Y[o][k] = fmaf(sv, BANK.w[k][56 + d], Y[o][k]);
                        }
                    }
                }
            }
            #pragma unroll
            for (int e = 0; e < 4; ++e) { Lp[e] = Lc[e]; Rp[e] = Rc[e]; }
        }

        // ---------- phase 4: softmax (e4 = 1) + mix + store ----------
        float* op = out + ((size_t)bb * T + tb) * C + c0 + tx;
        #pragma unroll
        for (int o = 0; o < RCHUNK; ++o) {
            float e0 = ew[o][0], e1 = ew[o][1], e2 = ew[o][2], e3 = ew[o][3];
            float sum = ((e0 + e1) + (e2 + e3)) + 1.0f;
            float dot = fmaf(e0, Y[o][0], Y[o][4]);
            dot = fmaf(e1, Y[o][1], dot);
            dot = fmaf(e2, Y[o][2], dot);
            dot = fmaf(e3, Y[o][3], dot);
            op[(size_t)o * C] = dot * rcpf(sum);
        }
    }
}

// ---------------- launch ----------------
extern "C" void kernel_launch(void* const* d_in, const int* in_sizes, int n_in,
                              void* d_out, int out_size) {
    const float* x  = (const float*)d_in[0];
    const float* W1 = (const float*)d_in[1];
    const float* b1 = (const float*)d_in[2];
    const float* W2 = (const float*)d_in[3];
    const float* b2 = (const float*)d_in[4];
    float* out = (float*)d_out;

    const int B = 16, T = 4096, C = 256;
    size_t smem = (size_t)(WSF + 576) * sizeof(float);
    cudaFuncSetAttribute(agt_kernel, cudaFuncAttributeMaxDynamicSharedMemorySize, (int)smem);

    dim3 grid(C / CT, T / TT, B);
    dim3 block(CT, NTY);
    agt_kernel<<<grid, block, smem>>>(x, W1, b1, W2, b2, out, B, T, C);
}

// round 12
// speedup vs baseline: 2.2754x; 1.0182x over previous
#include <cuda_runtime.h>
#include <math.h>

#define TT    256    // t-rows per block tile
#define CT    32     // channels per block tile
#define HALO  56     // max conv radius
#define ROWS  (TT + 2*HALO)   // 368
#define ROWSP 372    // padded column stride (mult of 4 for LDS.128 alignment)
#define NTHREADS 256
#define NTY   8      // t-groups per block
#define RCHUNK 4     // outputs per thread per chunk
#define WSF   (CT * ROWSP)    // float offset of weights in smem (16B aligned)

typedef unsigned long long ull;

// ---------------- packed f32x2 helpers ----------------
__device__ __forceinline__ ull ffma2(ull a, ull b, ull c) {
    ull d; asm("fma.rn.f32x2 %0,%1,%2,%3;" : "=l"(d) : "l"(a), "l"(b), "l"(c)); return d;
}
__device__ __forceinline__ ull fmul2(ull a, ull b) {
    ull d; asm("mul.rn.f32x2 %0,%1,%2;" : "=l"(d) : "l"(a), "l"(b)); return d;
}
__device__ __forceinline__ ull pk2(float lo, float hi) {
    ull d; asm("mov.b64 %0,{%1,%2};" : "=l"(d) : "f"(lo), "f"(hi)); return d;
}
__device__ __forceinline__ void upk2(ull a, float& lo, float& hi) {
    asm("mov.b64 {%0,%1},%2;" : "=f"(lo), "=f"(hi) : "l"(a));
}
__device__ __forceinline__ float rcpf(float x) {
    float r; asm("rcp.approx.f32 %0,%1;" : "=f"(r) : "f"(x)); return r;
}
__device__ __forceinline__ float ex2f(float x) {
    float r; asm("ex2.approx.f32 %0,%1;" : "=f"(r) : "f"(x)); return r;
}
__device__ __forceinline__ float tanhf_a(float x) {
    float r; asm("tanh.approx.f32 %0,%1;" : "=f"(r) : "f"(x)); return r;
}

// ---------------- compile-time Gaussian bank ----------------
__host__ __device__ constexpr double cexp_(double x) {
    double y = x / 256.0;
    double s = 1.0, term = 1.0;
    for (int n = 1; n <= 24; ++n) { term = term * y / (double)n; s += term; }
    for (int i = 0; i < 8; ++i) s = s * s;
    return s;
}

struct BankT { float w[5][113]; };

__host__ __device__ constexpr BankT make_bank() {
    BankT b{};
    double sig[5] = {2.5, 4.0, 6.0, 9.0, 14.0};
    for (int k = 0; k < 5; ++k) {
        double s = sig[k];
        int r = (int)(4.0 * s);          // 10,16,24,36,56
        double sum = 0.0;
        for (int d = -r; d <= r; ++d) sum += cexp_(-0.5 * ((double)d / s) * ((double)d / s));
        for (int d = -r; d <= r; ++d)
            b.w[k][56 + d] = (float)(cexp_(-0.5 * ((double)d / s) * ((double)d / s)) / sum);
    }
    return b;
}

// ---------------- kernel ----------------
__global__ void __launch_bounds__(NTHREADS, 4)
agt_kernel(const float* __restrict__ x, const float* __restrict__ W1,
           const float* __restrict__ b1, const float* __restrict__ W2,
           const float* __restrict__ b2, float* __restrict__ out,
           int B, int T, int C)
{
    constexpr BankT BANK = make_bank();
    constexpr int RAD[5] = {10, 16, 24, 36, 56};

    extern __shared__ float sm[];
    float* S   = sm;               // transposed tile: S[cc*ROWSP + r]
    float* ws2 = sm + WSF;         // weights: 32 j-blocks of 16 floats + b2d(8)

    const int tx  = threadIdx.x;           // channel in tile (0..31) = lane
    const int ty  = threadIdx.y;           // t-group (0..7) = warp id
    const int tid = ty * CT + tx;
    const int c0  = blockIdx.x * CT;
    const int t0  = blockIdx.y * TT;
    const int bb  = blockIdx.z;

    // --- stage weights: per-j 16-float blocks, each value duplicated (lo,hi):
    // block j: [W1m | W1v | W1x | b1 | W2d0 | W2d1 | W2d2 | W2d3] (8 pairs)
    // then b2d: 4 pairs at float offset 512.
    // 4-logit softmax: W2d[j][k] = (W2[j][k]-W2[j][4]) * 0.5*log2(e),
    //                  b2d[k]    = (b2[k]-b2[4]) * log2(e);   e4 == 1.
    for (int i = tid; i < 520; i += NTHREADS) {
        float v;
        if (i < 512) {
            int j = i >> 4, pr = (i >> 1) & 7;
            if      (pr < 3)  v = W1[pr * 32 + j];
            else if (pr == 3) v = b1[j];
            else {
                int k = pr - 4;
                v = (W2[j * 5 + k] - W2[j * 5 + 4]) * (0.5f * 1.4426950408889634f);
            }
        } else {
            int k = (i - 512) >> 1;
            v = (b2[k] - b2[4]) * 1.4426950408889634f;
        }
        ws2[i] = v;
    }

    // --- stage x tile TRANSPOSED (zero padded outside [0,T)) ---
    const float* xb = x + ((size_t)bb * T) * C + c0;
    for (int idx = tid; idx < ROWS * CT; idx += NTHREADS) {
        int r  = idx >> 5;          // row
        int cc = idx & (CT - 1);    // channel (lane) -> coalesced gmem read
        int g  = t0 - HALO + r;
        float v = 0.0f;
        if (g >= 0 && g < T) v = xb[(size_t)g * C + cc];
        S[cc * ROWSP + r] = v;
    }
    __syncthreads();

    const float* colp = S + tx * ROWSP;    // this thread's channel column
    const ull*   wp   = (const ull*)ws2;

    // tanh-GELU: u = z*(CK1 + CK2*z^2)
    const ull CK1 = pk2(0.7978845608f, 0.7978845608f);
    const ull CK2 = pk2(0.0356774081f, 0.0356774081f);

    const bool interior = (t0 >= 8) && (t0 + TT + 8 <= T);
    const int  lb0 = ty * (TT / NTY);      // first local output row of this warp
    const int  tb0 = t0 + lb0;

    // ---- carried sliding sums: init window of virtual output (tb0-1)
    float s = 0.0f, s2 = 0.0f;
    if (interior) {
        #pragma unroll
        for (int u = -8; u <= 7; ++u) {
            float w = colp[lb0 + HALO + u];
            s += w; s2 += w * w;
        }
    } else {
        #pragma unroll
        for (int u = -8; u <= 7; ++u) {
            int g = tb0 + u;
            g = (g < 0)  ? -g              : g;
            g = (g >= T) ? (2 * T - 2 - g) : g;
            float w = colp[g - t0 + HALO];
            s += w; s2 += w * w;
        }
    }

    #pragma unroll 1
    for (int chunk = 0; chunk < TT / (NTY * RCHUNK); ++chunk) {   // 8 iterations
        const int lb = lb0 + chunk * RCHUNK;   // local first output row
        const int tb = t0 + lb;                // global first output row
        const int b0 = lb + HALO;              // tile row of output 0 (b0 % 4 == 0)

        // center taps (also xv): rows b0..b0+3, 16B aligned
        const float4 cq = *(const float4*)&colp[b0];
        const float cqa[4] = {cq.x, cq.y, cq.z, cq.w};

        // ---------- phase 1: carried mean / var ----------
        float m[RCHUNK], va[RCHUNK];
        if (interior) {
            #pragma unroll
            for (int i = 0; i < RCHUNK; ++i) {
                float wa = colp[b0 + i + 8];
                float wr = colp[b0 + i - 8];
                s  += wa - wr;
                s2 += wa * wa - wr * wr;
                float mm  = s  * (1.0f / 16.0f);
                float m2v = s2 * (1.0f / 16.0f);
                m[i]  = mm;
                va[i] = fmaxf(m2v - mm * mm, 0.0f);
            }
        } else {
            #pragma unroll
            for (int i = 0; i < RCHUNK; ++i) {
                int ga = tb + i + 8;  ga = (ga >= T) ? (2 * T - 2 - ga) : ga;
                int gr = tb + i - 8;  gr = (gr < 0)  ? -gr              : gr;
                float wa = colp[ga - t0 + HALO];
                float wr = colp[gr - t0 + HALO];
                s  += wa - wr;
                s2 += wa * wa - wr * wr;
                float mm  = s  * (1.0f / 16.0f);
                float m2v = s2 * (1.0f / 16.0f);
                m[i]  = mm;
                va[i] = fmaxf(m2v - mm * mm, 0.0f);
            }
        }

        // pack features into f32x2 pairs (i, i+1)
        ull m2[2], v2p[2], x2[2];
        #pragma unroll
        for (int p = 0; p < 2; ++p) {
            m2[p]  = pk2(m[2 * p],  m[2 * p + 1]);
            v2p[p] = pk2(va[2 * p], va[2 * p + 1]);
            x2[p]  = pk2(cqa[2 * p], cqa[2 * p + 1]);
        }

        // ---------- phase 2: conditioner MLP, packed tanh.approx GELU ----------
        ull lg[2][4];
        #pragma unroll
        for (int p = 0; p < 2; ++p)
            #pragma unroll
            for (int k = 0; k < 4; ++k) lg[p][k] = wp[256 + k];   // b2d pairs

        #pragma unroll 2
        for (int j = 0; j < 32; ++j) {
            // 4 broadcast LDS.128: whole j-block (8 weight pairs) in 4 wavefronts
            const ull* wj = wp + 8 * j;
            ull w1m = wj[0], w1v = wj[1], w1x = wj[2], bj = wj[3];
            ull w20 = wj[4], w21 = wj[5], w22 = wj[6], w23 = wj[7];
            #pragma unroll
            for (int p = 0; p < 2; ++p) {
                ull z  = ffma2(m2[p], w1m, ffma2(v2p[p], w1v, ffma2(x2[p], w1x, bj)));
                ull zz = fmul2(z, z);
                ull u  = fmul2(z, ffma2(zz, CK2, CK1));
                float ul, uh; upk2(u, ul, uh);
                ull th = pk2(tanhf_a(ul), tanhf_a(uh));
                ull g  = ffma2(z, th, z);        // g' = z*(1 + tanh(u)) = 2*gelu
                lg[p][0] = ffma2(g, w20, lg[p][0]);
                lg[p][1] = ffma2(g, w21, lg[p][1]);
                lg[p][2] = ffma2(g, w22, lg[p][2]);
                lg[p][3] = ffma2(g, w23, lg[p][3]);
            }
        }

        // logits -> unnormalized softmax weights (e4 == 1), frees lg
        float ew[RCHUNK][4];
        #pragma unroll
        for (int p = 0; p < 2; ++p) {
            float lo, hi;
            #pragma unroll
            for (int k = 0; k < 4; ++k) {
                upk2(lg[p][k], lo, hi);
                ew[2 * p][k]     = ex2f(lo);
                ew[2 * p + 1][k] = ex2f(hi);
            }
        }

        // ---------- phase 3: symmetric conv, float4-streamed columns ----------
        float Y[RCHUNK][5];
        #pragma unroll
        for (int o = 0; o < RCHUNK; ++o)
            #pragma unroll
            for (int k = 0; k < 5; ++k) Y[o][k] = cqa[o] * BANK.w[k][56];

        float Lp[4] = {cqa[0], cqa[1], cqa[2], cqa[3]};  // rows b0..b0+3
        float Rp[4] = {cqa[0], cqa[1], cqa[2], cqa[3]};  // rows b0..b0+3
        #pragma unroll
        for (int g14 = 0; g14 < 14; ++g14) {
            const float4 lq = *(const float4*)&colp[b0 - 4 * g14 - 4];
            const float4 rq = *(const float4*)&colp[b0 + 4 * g14 + 4];
            const float Lc[4] = {lq.x, lq.y, lq.z, lq.w};
            const float Rc[4] = {rq.x, rq.y, rq.z, rq.w};
            #pragma unroll
            for (int dd = 1; dd <= 4; ++dd) {
                const int d = 4 * g14 + dd;
                #pragma unroll
                for (int o = 0; o < RCHUNK; ++o) {
                    const int el = 4 - dd + o;          // L row b0-d+o
                    const int er = dd + o;              // R row b0+d+o
                    float Lv = (el < 4) ? Lc[el] : Lp[el - 4];
                    float Rv = (er < 4) ? Rp[er] : Rc[er - 4];
                    if (d > RAD[3]) {
                        // single sigma tail: 2 FFMA-imm (rt1) beat FADD+FFMA
                        Y[o][4] = fmaf(Lv, BANK.w[4][56 + d], Y[o][4]);
                        Y[o][4] = fmaf(Rv, BANK.w[4][56 + d], Y[o][4]);
                    } else {
                        float sv = Lv + Rv;
                        #pragma unroll
                        for (int k = 0; k < 5; ++k) {
                            if (d <= RAD[k])
                                Y[o][k] = fmaf(sv, BANK.w[k][56 + d], Y[o][k]);
                        }
                    }
                }
            }
            #pragma unroll
            for (int e = 0; e < 4; ++e) { Lp[e] = Lc[e]; Rp[e] = Rc[e]; }
        }

        // ---------- phase 4: softmax (e4 = 1) + mix + store ----------
        float* op = out + ((size_t)bb * T + tb) * C + c0 + tx;
        #pragma unroll
        for (int o = 0; o < RCHUNK; ++o) {
            float e0 = ew[o][0], e1 = ew[o][1], e2 = ew[o][2], e3 = ew[o][3];
            float sum = ((e0 + e1) + (e2 + e3)) + 1.0f;
            float dot = fmaf(e0, Y[o][0], Y[o][4]);
            dot = fmaf(e1, Y[o][1], dot);
            dot = fmaf(e2, Y[o][2], dot);
            dot = fmaf(e3, Y[o][3], dot);
            op[(size_t)o * C] = dot * rcpf(sum);
        }
    }
}

// ---------------- launch ----------------
extern "C" void kernel_launch(void* const* d_in, const int* in_sizes, int n_in,
                              void* d_out, int out_size) {
    const float* x  = (const float*)d_in[0];
    const float* W1 = (const float*)d_in[1];
    const float* b1 = (const float*)d_in[2];
    const float* W2 = (const float*)d_in[3];
    const float* b2 = (const float*)d_in[4];
    float* out = (float*)d_out;

    const int B = 16, T = 4096, C = 256;
    size_t smem = (size_t)(WSF + 576) * sizeof(float);
    cudaFuncSetAttribute(agt_kernel, cudaFuncAttributeMaxDynamicSharedMemorySize, (int)smem);

    dim3 grid(C / CT, T / TT, B);
    dim3 block(CT, NTY);
    agt_kernel<<<grid, block, smem>>>(x, W1, b1, W2, b2, out, B, T, C);
}

// round 13
// speedup vs baseline: 2.2802x; 1.0021x over previous
#include <cuda_runtime.h>
#include <math.h>

#define TT    256    // t-rows per block tile
#define CT    32     // channels per block tile
#define HALO  56     // max conv radius
#define ROWS  (TT + 2*HALO)   // 368
#define ROWSP 372    // padded column stride (mult of 4 for LDS.128 alignment)
#define NTHREADS 256
#define NTY   8      // t-groups per block
#define RCHUNK 4     // outputs per thread per chunk
#define WSF   (CT * ROWSP)    // float offset of weights in smem (16B aligned)

typedef unsigned long long ull;

// ---------------- packed f32x2 helpers ----------------
__device__ __forceinline__ ull ffma2(ull a, ull b, ull c) {
    ull d; asm("fma.rn.f32x2 %0,%1,%2,%3;" : "=l"(d) : "l"(a), "l"(b), "l"(c)); return d;
}
__device__ __forceinline__ ull fmul2(ull a, ull b) {
    ull d; asm("mul.rn.f32x2 %0,%1,%2;" : "=l"(d) : "l"(a), "l"(b)); return d;
}
__device__ __forceinline__ ull pk2(float lo, float hi) {
    ull d; asm("mov.b64 %0,{%1,%2};" : "=l"(d) : "f"(lo), "f"(hi)); return d;
}
__device__ __forceinline__ void upk2(ull a, float& lo, float& hi) {
    asm("mov.b64 {%0,%1},%2;" : "=f"(lo), "=f"(hi) : "l"(a));
}
__device__ __forceinline__ float rcpf(float x) {
    float r; asm("rcp.approx.f32 %0,%1;" : "=f"(r) : "f"(x)); return r;
}
__device__ __forceinline__ float ex2f(float x) {
    float r; asm("ex2.approx.f32 %0,%1;" : "=f"(r) : "f"(x)); return r;
}
__device__ __forceinline__ float tanhf_a(float x) {
    float r; asm("tanh.approx.f32 %0,%1;" : "=f"(r) : "f"(x)); return r;
}
// a + b as FFMA-imm (rt 1 vs FADD rt 2); exact: a*1.0+b
__device__ __forceinline__ float fadd1(float a, float b) {
    float r; asm("fma.rn.f32 %0,%1,0f3F800000,%2;" : "=f"(r) : "f"(a), "f"(b)); return r;
}
// c - a as FFMA-imm: a*(-1.0)+c
__device__ __forceinline__ float fnma1(float a, float c) {
    float r; asm("fma.rn.f32 %0,%1,0fBF800000,%2;" : "=f"(r) : "f"(a), "f"(c)); return r;
}
// v * imm as FFMA-imm with +0.0 addend (rt 1)
__device__ __forceinline__ float fmul1(float v, float imm) {
    float r; asm("fma.rn.f32 %0,%1,%2,0f00000000;" : "=f"(r) : "f"(v), "f"(imm)); return r;
}

// ---------------- compile-time Gaussian bank ----------------
__host__ __device__ constexpr double cexp_(double x) {
    double y = x / 256.0;
    double s = 1.0, term = 1.0;
    for (int n = 1; n <= 24; ++n) { term = term * y / (double)n; s += term; }
    for (int i = 0; i < 8; ++i) s = s * s;
    return s;
}

struct BankT { float w[5][113]; };

__host__ __device__ constexpr BankT make_bank() {
    BankT b{};
    double sig[5] = {2.5, 4.0, 6.0, 9.0, 14.0};
    for (int k = 0; k < 5; ++k) {
        double s = sig[k];
        int r = (int)(4.0 * s);          // 10,16,24,36,56
        double sum = 0.0;
        for (int d = -r; d <= r; ++d) sum += cexp_(-0.5 * ((double)d / s) * ((double)d / s));
        for (int d = -r; d <= r; ++d)
            b.w[k][56 + d] = (float)(cexp_(-0.5 * ((double)d / s) * ((double)d / s)) / sum);
    }
    return b;
}

// ---------------- kernel ----------------
__global__ void __launch_bounds__(NTHREADS, 4)
agt_kernel(const float* __restrict__ x, const float* __restrict__ W1,
           const float* __restrict__ b1, const float* __restrict__ W2,
           const float* __restrict__ b2, float* __restrict__ out,
           int B, int T, int C)
{
    constexpr BankT BANK = make_bank();
    constexpr int RAD[5] = {10, 16, 24, 36, 56};

    extern __shared__ float sm[];
    float* S   = sm;               // transposed tile: S[cc*ROWSP + r]
    float* ws2 = sm + WSF;         // weights: 32 j-blocks of 16 floats + b2d(8)

    const int tx  = threadIdx.x;           // channel in tile (0..31) = lane
    const int ty  = threadIdx.y;           // t-group (0..7) = warp id
    const int tid = ty * CT + tx;
    const int c0  = blockIdx.x * CT;
    const int t0  = blockIdx.y * TT;
    const int bb  = blockIdx.z;

    // --- stage weights: per-j 16-float blocks, each value duplicated (lo,hi):
    // block j: [W1m | W1v | W1x | b1 | W2d0 | W2d1 | W2d2 | W2d3] (8 pairs)
    // then b2d: 4 pairs at float offset 512.
    // 4-logit softmax: W2d[j][k] = (W2[j][k]-W2[j][4]) * 0.5*log2(e),
    //                  b2d[k]    = (b2[k]-b2[4]) * log2(e);   e4 == 1.
    for (int i = tid; i < 520; i += NTHREADS) {
        float v;
        if (i < 512) {
            int j = i >> 4, pr = (i >> 1) & 7;
            if      (pr < 3)  v = W1[pr * 32 + j];
            else if (pr == 3) v = b1[j];
            else {
                int k = pr - 4;
                v = (W2[j * 5 + k] - W2[j * 5 + 4]) * (0.5f * 1.4426950408889634f);
            }
        } else {
            int k = (i - 512) >> 1;
            v = (b2[k] - b2[4]) * 1.4426950408889634f;
        }
        ws2[i] = v;
    }

    // --- stage x tile TRANSPOSED (zero padded outside [0,T)) ---
    const float* xb = x + ((size_t)bb * T) * C + c0;
    for (int idx = tid; idx < ROWS * CT; idx += NTHREADS) {
        int r  = idx >> 5;          // row
        int cc = idx & (CT - 1);    // channel (lane) -> coalesced gmem read
        int g  = t0 - HALO + r;
        float v = 0.0f;
        if (g >= 0 && g < T) v = xb[(size_t)g * C + cc];
        S[cc * ROWSP + r] = v;
    }
    __syncthreads();

    const float* colp = S + tx * ROWSP;    // this thread's channel column
    const ull*   wp   = (const ull*)ws2;

    // tanh-GELU: u = z*(CK1 + CK2*z^2)
    const ull CK1 = pk2(0.7978845608f, 0.7978845608f);
    const ull CK2 = pk2(0.0356774081f, 0.0356774081f);

    const bool interior = (t0 >= 8) && (t0 + TT + 8 <= T);
    const int  lb0 = ty * (TT / NTY);      // first local output row of this warp
    const int  tb0 = t0 + lb0;

    // ---- carried sliding sums: init window of virtual output (tb0-1)
    float s = 0.0f, s2 = 0.0f;
    if (interior) {
        #pragma unroll
        for (int u = -8; u <= 7; ++u) {
            float w = colp[lb0 + HALO + u];
            s  = fadd1(w, s);
            s2 = fmaf(w, w, s2);
        }
    } else {
        #pragma unroll
        for (int u = -8; u <= 7; ++u) {
            int g = tb0 + u;
            g = (g < 0)  ? -g              : g;
            g = (g >= T) ? (2 * T - 2 - g) : g;
            float w = colp[g - t0 + HALO];
            s  = fadd1(w, s);
            s2 = fmaf(w, w, s2);
        }
    }

    #pragma unroll 1
    for (int chunk = 0; chunk < TT / (NTY * RCHUNK); ++chunk) {   // 8 iterations
        const int lb = lb0 + chunk * RCHUNK;   // local first output row
        const int tb = t0 + lb;                // global first output row
        const int b0 = lb + HALO;              // tile row of output 0 (b0 % 4 == 0)

        // center taps (also xv): rows b0..b0+3, 16B aligned
        const float4 cq = *(const float4*)&colp[b0];
        const float cqa[4] = {cq.x, cq.y, cq.z, cq.w};

        // ---------- phase 1: carried mean / var (FFMA-imm updates) ----------
        float m[RCHUNK], va[RCHUNK];
        if (interior) {
            #pragma unroll
            for (int i = 0; i < RCHUNK; ++i) {
                float wa = colp[b0 + i + 8];
                float wr = colp[b0 + i - 8];
                s  = fadd1(wa, fnma1(wr, s));
                s2 = fmaf(wa, wa, s2);
                s2 = fmaf(wr, -wr, s2);
                float mm  = fmul1(s,  1.0f / 16.0f);
                float m2v = fmul1(s2, 1.0f / 16.0f);
                m[i]  = mm;
                va[i] = fmaxf(fmaf(-mm, mm, m2v), 0.0f);
            }
        } else {
            #pragma unroll
            for (int i = 0; i < RCHUNK; ++i) {
                int ga = tb + i + 8;  ga = (ga >= T) ? (2 * T - 2 - ga) : ga;
                int gr = tb + i - 8;  gr = (gr < 0)  ? -gr              : gr;
                float wa = colp[ga - t0 + HALO];
                float wr = colp[gr - t0 + HALO];
                s  = fadd1(wa, fnma1(wr, s));
                s2 = fmaf(wa, wa, s2);
                s2 = fmaf(wr, -wr, s2);
                float mm  = fmul1(s,  1.0f / 16.0f);
                float m2v = fmul1(s2, 1.0f / 16.0f);
                m[i]  = mm;
                va[i] = fmaxf(fmaf(-mm, mm, m2v), 0.0f);
            }
        }

        // pack features into f32x2 pairs (i, i+1)
        ull m2[2], v2p[2], x2[2];
        #pragma unroll
        for (int p = 0; p < 2; ++p) {
            m2[p]  = pk2(m[2 * p],  m[2 * p + 1]);
            v2p[p] = pk2(va[2 * p], va[2 * p + 1]);
            x2[p]  = pk2(cqa[2 * p], cqa[2 * p + 1]);
        }

        // ---------- phase 2: conditioner MLP, packed tanh.approx GELU ----------
        ull lg[2][4];
        #pragma unroll
        for (int p = 0; p < 2; ++p)
            #pragma unroll
            for (int k = 0; k < 4; ++k) lg[p][k] = wp[256 + k];   // b2d pairs

        #pragma unroll 4
        for (int j = 0; j < 32; ++j) {
            // 4 broadcast LDS.128: whole j-block (8 weight pairs) in 4 wavefronts
            const ull* wj = wp + 8 * j;
            ull w1m = wj[0], w1v = wj[1], w1x = wj[2], bj = wj[3];
            ull w20 = wj[4], w21 = wj[5], w22 = wj[6], w23 = wj[7];
            #pragma unroll
            for (int p = 0; p < 2; ++p) {
                ull z  = ffma2(m2[p], w1m, ffma2(v2p[p], w1v, ffma2(x2[p], w1x, bj)));
                ull zz = fmul2(z, z);
                ull u  = fmul2(z, ffma2(zz, CK2, CK1));
                float ul, uh; upk2(u, ul, uh);
                ull th = pk2(tanhf_a(ul), tanhf_a(uh));
                ull g  = ffma2(z, th, z);        // g' = z*(1 + tanh(u)) = 2*gelu
                lg[p][0] = ffma2(g, w20, lg[p][0]);
                lg[p][1] = ffma2(g, w21, lg[p][1]);
                lg[p][2] = ffma2(g, w22, lg[p][2]);
                lg[p][3] = ffma2(g, w23, lg[p][3]);
            }
        }

        // logits -> unnormalized softmax weights (e4 == 1), frees lg
        float ew[RCHUNK][4];
        #pragma unroll
        for (int p = 0; p < 2; ++p) {
            float lo, hi;
            #pragma unroll
            for (int k = 0; k < 4; ++k) {
                upk2(lg[p][k], lo, hi);
                ew[2 * p][k]     = ex2f(lo);
                ew[2 * p + 1][k] = ex2f(hi);
            }
        }

        // ---------- phase 3: symmetric conv, float4-streamed columns ----------
        float Y[RCHUNK][5];
        #pragma unroll
        for (int o = 0; o < RCHUNK; ++o)
            #pragma unroll
            for (int k = 0; k < 5; ++k) Y[o][k] = fmul1(cqa[o], BANK.w[k][56]);

        float Lp[4] = {cqa[0], cqa[1], cqa[2], cqa[3]};  // rows b0..b0+3
        float Rp[4] = {cqa[0], cqa[1], cqa[2], cqa[3]};  // rows b0..b0+3
        #pragma unroll
        for (int g14 = 0; g14 < 14; ++g14) {
            const float4 lq = *(const float4*)&colp[b0 - 4 * g14 - 4];
            const float4 rq = *(const float4*)&colp[b0 + 4 * g14 + 4];
            const float Lc[4] = {lq.x, lq.y, lq.z, lq.w};
            const float Rc[4] = {rq.x, rq.y, rq.z, rq.w};
            #pragma unroll
            for (int dd = 1; dd <= 4; ++dd) {
                const int d = 4 * g14 + dd;
                #pragma unroll
                for (int o = 0; o < RCHUNK; ++o) {
                    const int el = 4 - dd + o;          // L row b0-d+o
                    const int er = dd + o;              // R row b0+d+o
                    float Lv = (el < 4) ? Lc[el] : Lp[el - 4];
                    float Rv = (er < 4) ? Rp[er] : Rc[er - 4];
                    if (d > RAD[3]) {
                        // single sigma tail: 2 FFMA-imm (rt1)
                        Y[o][4] = fmaf(Lv, BANK.w[4][56 + d], Y[o][4]);
                        Y[o][4] = fmaf(Rv, BANK.w[4][56 + d], Y[o][4]);
                    } else {
                        float sv = fadd1(Lv, Rv);       // FFMA-imm, rt1
                        #pragma unroll
                        for (int k = 0; k < 5; ++k) {
                            if (d <= RAD[k])
                                Y[o][k] = fmaf(sv, BANK.w[k][56 + d], Y[o][k]);
                        }
                    }
                }
            }
            #pragma unroll
            for (int e = 0; e < 4; ++e) { Lp[e] = Lc[e]; Rp[e] = Rc[e]; }
        }

        // ---------- phase 4: softmax (e4 = 1) + mix + store ----------
        float* op = out + ((size_t)bb * T + tb) * C + c0 + tx;
        const float one = 1.0f;
        #pragma unroll
        for (int o = 0; o < RCHUNK; ++o) {
            float e0 = ew[o][0], e1 = ew[o][1], e2 = ew[o][2], e3 = ew[o][3];
            float sum = fadd1(e0, fadd1(e1, fadd1(e2, fadd1(e3, one))));
            float dot = fmaf(e0, Y[o][0], Y[o][4]);
            dot = fmaf(e1, Y[o][1], dot);
            dot = fmaf(e2, Y[o][2], dot);
            dot = fmaf(e3, Y[o][3], dot);
            op[(size_t)o * C] = dot * rcpf(sum);
        }
    }
}

// ---------------- launch ----------------
extern "C" void kernel_launch(void* const* d_in, const int* in_sizes, int n_in,
                              void* d_out, int out_size) {
    const float* x  = (const float*)d_in[0];
    const float* W1 = (const float*)d_in[1];
    const float* b1 = (const float*)d_in[2];
    const float* W2 = (const float*)d_in[3];
    const float* b2 = (const float*)d_in[4];
    float* out = (float*)d_out;

    const int B = 16, T = 4096, C = 256;
    size_t smem = (size_t)(WSF + 576) * sizeof(float);
    cudaFuncSetAttribute(agt_kernel, cudaFuncAttributeMaxDynamicSharedMemorySize, (int)smem);

    dim3 grid(C / CT, T / TT, B);
    dim3 block(CT, NTY);
    agt_kernel<<<grid, block, smem>>>(x, W1, b1, W2, b2, out, B, T, C);
}